// round 7
// baseline (speedup 1.0000x reference)
#include <cuda_runtime.h>
#include <cstdint>

// Problem constants (fixed by dataset)
#define MAXN   50000
#define NFEAT  512
#define FHID   256
#define FOUT   64

// Scratch (device globals: allocation-free per harness rules)
__device__ float g_h1 [MAXN * FHID];    // x @ W1
__device__ float g_h2 [MAXN * FHID];    // spmm(h1) + b1  (relu+rna applied on read in GEMM2)
__device__ float g_h3 [MAXN * FOUT];    // relu(h2) @ W2
__device__ float g_w1t[FHID * NFEAT];   // W1^T, tf32-rounded
__device__ float g_w2t[FOUT * FHID];    // W2^T, tf32-rounded

// ===========================================================================
// helpers
// ===========================================================================
__device__ __forceinline__ uint32_t smem_u32(const void* p) {
    uint32_t a;
    asm("{ .reg .u64 t; cvta.to.shared.u64 t, %1; cvt.u32.u64 %0, t; }"
        : "=r"(a) : "l"(p));
    return a;
}
__device__ __forceinline__ float rna_tf32(float f) {
    uint32_t u;
    asm("cvt.rna.tf32.f32 %0, %1;" : "=r"(u) : "f"(f));
    return __uint_as_float(u);
}
__device__ __forceinline__ void cp16(uint32_t dst, const void* src) {
    asm volatile("cp.async.cg.shared.global [%0], [%1], 16;"
                 :: "r"(dst), "l"(src) : "memory");
}
#define CP_COMMIT() asm volatile("cp.async.commit_group;" ::: "memory")
#define CP_WAIT0()  asm volatile("cp.async.wait_group 0;" ::: "memory")

// vectorized global reduction (PTX 8.1+, sm_90+ base feature)
__device__ __forceinline__ void red4(float* addr, float4 v) {
    asm volatile("red.global.add.v4.f32 [%0], {%1,%2,%3,%4};"
                 :: "l"(addr), "f"(v.x), "f"(v.y), "f"(v.z), "f"(v.w) : "memory");
}

// mma.sync m16n8k8 tf32 (base PTX, works on compute_103 target)
__device__ __forceinline__ void mma8(float* d, const uint32_t* a, const uint32_t* b) {
    asm volatile(
        "mma.sync.aligned.m16n8k8.row.col.f32.tf32.tf32.f32 "
        "{%0,%1,%2,%3}, {%4,%5,%6,%7}, {%8,%9}, {%0,%1,%2,%3};"
        : "+f"(d[0]), "+f"(d[1]), "+f"(d[2]), "+f"(d[3])
        : "r"(a[0]), "r"(a[1]), "r"(a[2]), "r"(a[3]), "r"(b[0]), "r"(b[1]));
}

// ===========================================================================
// Big-warp-tile tf32 GEMM (for GEMM1):  C[M,Ntot] = op(A)[M,K] @ Bt[Ntot,K]^T
//   BM=128, BN=128, BK=16; 128 threads = 4 warps (2M x 2N); warp tile 64x64.
// ===========================================================================
template<int AMODE>
__global__ void __launch_bounds__(128)
gemm_mma_big(const float* __restrict__ A, const float* __restrict__ Bt,
             float* __restrict__ C, int M, int K, int Ntot)
{
    constexpr int BM = 128, BN = 128, BK = 16, LDS = 20;
    __shared__ float As[2][BM * LDS];
    __shared__ float Bs[2][BN * LDS];

    const int tid  = threadIdx.x;
    const int lane = tid & 31, wid = tid >> 5;
    const int g    = lane >> 2, tig = lane & 3;
    const int wm0  = (wid >> 1) * 64;            // warp M origin (0/64)
    const int wn0  = (wid & 1) * 64;             // warp N origin (0/64)
    const int blockM = blockIdx.y * BM;
    const int blockN = blockIdx.x * BN;

    const int arow = tid >> 2;                   // 0..31 (A rows: arow + 32i)
    const int aq   = tid & 3;

    float acc[4][8][4];
    #pragma unroll
    for (int mt = 0; mt < 4; mt++)
        #pragma unroll
        for (int nt = 0; nt < 8; nt++)
            #pragma unroll
            for (int i = 0; i < 4; i++) acc[mt][nt][i] = 0.f;

    auto ldgA = [&](int c, float4* av) {
        const int k0 = c * BK;
        #pragma unroll
        for (int i = 0; i < 4; i++) {
            int r = blockM + arow + i * 32;
            if (r < M)
                av[i] = *reinterpret_cast<const float4*>(&A[(size_t)r * K + k0 + aq * 4]);
            else
                av[i] = make_float4(0.f, 0.f, 0.f, 0.f);
        }
    };
    auto stsA = [&](int buf, float4* av) {
        #pragma unroll
        for (int i = 0; i < 4; i++) {
            float4 v = av[i];
            if (AMODE == 2) {
                v.x = fmaxf(v.x, 0.f); v.y = fmaxf(v.y, 0.f);
                v.z = fmaxf(v.z, 0.f); v.w = fmaxf(v.w, 0.f);
            }
            if (AMODE >= 1) {
                v.x = rna_tf32(v.x); v.y = rna_tf32(v.y);
                v.z = rna_tf32(v.z); v.w = rna_tf32(v.w);
            }
            *reinterpret_cast<float4*>(&As[buf][(arow + i * 32) * LDS + aq * 4]) = v;
        }
    };
    auto cpB = [&](int c, int buf) {
        const int k0 = c * BK;
        #pragma unroll
        for (int i = 0; i < 4; i++) {
            int u = tid + i * 128;
            int r = u >> 2, q = u & 3;
            cp16(smem_u32(&Bs[buf][r * LDS + q * 4]),
                 &Bt[(size_t)(blockN + r) * K + k0 + q * 4]);
        }
        CP_COMMIT();
    };
    auto compute = [&](int buf) {
        #pragma unroll
        for (int ks = 0; ks < 2; ks++) {
            uint32_t a[4][4], b[8][2];
            #pragma unroll
            for (int mt = 0; mt < 4; mt++) {
                const float* p0 = &As[buf][(wm0 + mt * 16 + g) * LDS + ks * 8];
                const float* p1 = p0 + 8 * LDS;
                a[mt][0] = __float_as_uint(p0[tig]);
                a[mt][2] = __float_as_uint(p0[tig + 4]);
                a[mt][1] = __float_as_uint(p1[tig]);
                a[mt][3] = __float_as_uint(p1[tig + 4]);
            }
            #pragma unroll
            for (int nt = 0; nt < 8; nt++) {
                const float* pb = &Bs[buf][(wn0 + nt * 8 + g) * LDS + ks * 8];
                b[nt][0] = __float_as_uint(pb[tig]);
                b[nt][1] = __float_as_uint(pb[tig + 4]);
            }
            #pragma unroll
            for (int mt = 0; mt < 4; mt++)
                #pragma unroll
                for (int nt = 0; nt < 8; nt++)
                    mma8(acc[mt][nt], a[mt], b[nt]);
        }
    };

    // prologue
    {
        float4 av[4];
        ldgA(0, av);
        cpB(0, 0);
        stsA(0, av);
        CP_WAIT0();
        __syncthreads();
    }

    const int NC = K / BK;
    for (int c = 0; c < NC; c++) {
        float4 av[4];
        const bool more = (c + 1 < NC);
        if (more) {
            ldgA(c + 1, av);
            cpB(c + 1, (c + 1) & 1);
        }
        compute(c & 1);
        if (more) {
            stsA((c + 1) & 1, av);
            CP_WAIT0();
            __syncthreads();
        }
    }

    // epilogue
    #pragma unroll
    for (int mt = 0; mt < 4; mt++) {
        int r0 = blockM + wm0 + mt * 16 + g;
        int r1 = r0 + 8;
        #pragma unroll
        for (int nt = 0; nt < 8; nt++) {
            int cb = blockN + wn0 + nt * 8 + 2 * tig;
            if (r0 < M)
                *reinterpret_cast<float2*>(&C[(size_t)r0 * Ntot + cb]) =
                    make_float2(acc[mt][nt][0], acc[mt][nt][1]);
            if (r1 < M)
                *reinterpret_cast<float2*>(&C[(size_t)r1 * Ntot + cb]) =
                    make_float2(acc[mt][nt][2], acc[mt][nt][3]);
        }
    }
}

// ===========================================================================
// 8-warp tf32 GEMM (kept for GEMM2, BN=64):  C = op(A) @ Bt^T
// ===========================================================================
template<int BN, int WNT, int AMODE>
__global__ void __launch_bounds__(256)
gemm_mma(const float* __restrict__ A, const float* __restrict__ Bt,
         float* __restrict__ C, int M, int K, int Ntot)
{
    constexpr int BM = 128, BK = 16, LDS = 20;
    constexpr int NBI = (BN * BK / 4) / 256;
    __shared__ float As[2][BM * LDS];
    __shared__ float Bs[2][BN * LDS];

    const int tid  = threadIdx.x;
    const int lane = tid & 31, wid = tid >> 5;
    const int g    = lane >> 2, tig = lane & 3;
    const int wm0  = (wid >> 2) * 64;
    const int wn0  = (wid & 3) * (BN / 4);
    const int blockM = blockIdx.y * BM;
    const int blockN = blockIdx.x * BN;

    const int arow = tid >> 2;
    const int aq   = tid & 3;

    float acc[4][WNT][4];
    #pragma unroll
    for (int mt = 0; mt < 4; mt++)
        #pragma unroll
        for (int nt = 0; nt < WNT; nt++)
            #pragma unroll
            for (int i = 0; i < 4; i++) acc[mt][nt][i] = 0.f;

    auto ldgA = [&](int c, float4* av) {
        const int k0 = c * BK;
        #pragma unroll
        for (int i = 0; i < 2; i++) {
            int r = blockM + arow + i * 64;
            if (r < M)
                av[i] = *reinterpret_cast<const float4*>(&A[(size_t)r * K + k0 + aq * 4]);
            else
                av[i] = make_float4(0.f, 0.f, 0.f, 0.f);
        }
    };
    auto stsA = [&](int buf, float4* av) {
        #pragma unroll
        for (int i = 0; i < 2; i++) {
            float4 v = av[i];
            if (AMODE == 2) {
                v.x = fmaxf(v.x, 0.f); v.y = fmaxf(v.y, 0.f);
                v.z = fmaxf(v.z, 0.f); v.w = fmaxf(v.w, 0.f);
            }
            if (AMODE >= 1) {
                v.x = rna_tf32(v.x); v.y = rna_tf32(v.y);
                v.z = rna_tf32(v.z); v.w = rna_tf32(v.w);
            }
            *reinterpret_cast<float4*>(&As[buf][(arow + i * 64) * LDS + aq * 4]) = v;
        }
    };
    auto cpB = [&](int c, int buf) {
        const int k0 = c * BK;
        #pragma unroll
        for (int i = 0; i < NBI; i++) {
            int u = tid + i * 256;
            int r = u >> 2, q = u & 3;
            cp16(smem_u32(&Bs[buf][r * LDS + q * 4]),
                 &Bt[(size_t)(blockN + r) * K + k0 + q * 4]);
        }
        CP_COMMIT();
    };
    auto compute = [&](int buf) {
        #pragma unroll
        for (int ks = 0; ks < 2; ks++) {
            uint32_t a[4][4], b[WNT][2];
            #pragma unroll
            for (int mt = 0; mt < 4; mt++) {
                const float* p0 = &As[buf][(wm0 + mt * 16 + g) * LDS + ks * 8];
                const float* p1 = p0 + 8 * LDS;
                a[mt][0] = __float_as_uint(p0[tig]);
                a[mt][2] = __float_as_uint(p0[tig + 4]);
                a[mt][1] = __float_as_uint(p1[tig]);
                a[mt][3] = __float_as_uint(p1[tig + 4]);
            }
            #pragma unroll
            for (int nt = 0; nt < WNT; nt++) {
                const float* pb = &Bs[buf][(wn0 + nt * 8 + g) * LDS + ks * 8];
                b[nt][0] = __float_as_uint(pb[tig]);
                b[nt][1] = __float_as_uint(pb[tig + 4]);
            }
            #pragma unroll
            for (int mt = 0; mt < 4; mt++)
                #pragma unroll
                for (int nt = 0; nt < WNT; nt++)
                    mma8(acc[mt][nt], a[mt], b[nt]);
        }
    };

    {
        float4 av[2];
        ldgA(0, av);
        cpB(0, 0);
        stsA(0, av);
        CP_WAIT0();
        __syncthreads();
    }

    const int NC = K / BK;
    for (int c = 0; c < NC; c++) {
        float4 av[2];
        const bool more = (c + 1 < NC);
        if (more) {
            ldgA(c + 1, av);
            cpB(c + 1, (c + 1) & 1);
        }
        compute(c & 1);
        if (more) {
            stsA((c + 1) & 1, av);
            CP_WAIT0();
            __syncthreads();
        }
    }

    #pragma unroll
    for (int mt = 0; mt < 4; mt++) {
        int r0 = blockM + wm0 + mt * 16 + g;
        int r1 = r0 + 8;
        #pragma unroll
        for (int nt = 0; nt < WNT; nt++) {
            int cb = blockN + wn0 + nt * 8 + 2 * tig;
            if (r0 < M)
                *reinterpret_cast<float2*>(&C[(size_t)r0 * Ntot + cb]) =
                    make_float2(acc[mt][nt][0], acc[mt][nt][1]);
            if (r1 < M)
                *reinterpret_cast<float2*>(&C[(size_t)r1 * Ntot + cb]) =
                    make_float2(acc[mt][nt][2], acc[mt][nt][3]);
        }
    }
}

// ===========================================================================
// Elementwise kernels
// ===========================================================================
__global__ void transpose_round2(const float* __restrict__ w1, float* __restrict__ w1t,
                                 const float* __restrict__ w2, float* __restrict__ w2t,
                                 int sz1, int n1, int k1, int sz2, int n2, int k2)
{
    int i = blockIdx.x * blockDim.x + threadIdx.x;
    if (i < sz1) {
        int k = i / n1, n = i % n1;
        w1t[(size_t)n * k1 + k] = rna_tf32(w1[i]);
    } else if (i < sz1 + sz2) {
        int j = i - sz1;
        int k = j / n2, n = j % n2;
        w2t[(size_t)n * k2 + k] = rna_tf32(w2[j]);
    }
}

__global__ void init_bias4(float4* __restrict__ dst, const float4* __restrict__ bias,
                           int total4, int fmask4)
{
    int i = blockIdx.x * blockDim.x + threadIdx.x;
    if (i < total4) dst[i] = bias[i & fmask4];
}

// ---------------------------------------------------------------------------
// SpMM scatter (float4 lanes): dst[row[e]] += edge_w[e] * src[col[e]],
// row sorted ascending.  T = F/4 threads per edge-group, G groups per block.
// Batched-4 LDG.128 gathers (MLP=4, 40 regs -> high occupancy), register
// float4 accumulation across sorted-row runs, red.global.add.v4.f32 flush.
// ---------------------------------------------------------------------------
template<int F, int EPG, int G>
__global__ void __launch_bounds__((F / 4) * G)
spmm_scatter4(const float* __restrict__ src, const float* __restrict__ ew,
              const int* __restrict__ row, const int* __restrict__ col,
              float* __restrict__ dst, int E)
{
    constexpr int T = F / 4;
    __shared__ int   s_row[G][EPG];
    __shared__ uint2 s_cw[G][EPG];     // {col, edge_w bits}

    const int g = threadIdx.x / T;
    const int f = threadIdx.x % T;     // covers floats [4f, 4f+4)
    const long base = ((long)blockIdx.x * G + g) * EPG;

    long rem = (long)E - base;
    const int cnt = rem <= 0 ? 0 : (rem < EPG ? (int)rem : EPG);

    for (int i = f; i < cnt; i += T) {
        long e = base + i;
        s_row[g][i] = row[e];
        s_cw[g][i]  = make_uint2((unsigned)col[e], __float_as_uint(ew[e]));
    }
    __syncthreads();

    const float4* src4 = reinterpret_cast<const float4*>(src) + f;
    float4 acc = make_float4(0.f, 0.f, 0.f, 0.f);
    int    cur = -1;

    int i = 0;
    const int full = cnt & ~3;
    for (; i < full; i += 4) {
        int rr[4]; float w[4]; float4 v[4];
        #pragma unroll
        for (int j = 0; j < 4; j++) {              // 4 LDG.128 in flight
            rr[j] = s_row[g][i + j];
            uint2 cw = s_cw[g][i + j];
            w[j] = __uint_as_float(cw.y);
            v[j] = __ldg(&src4[(size_t)cw.x * T]);
        }
        #pragma unroll
        for (int j = 0; j < 4; j++) {              // register-only scan
            if (rr[j] != cur) {
                if (cur >= 0) red4(&dst[(size_t)cur * F + 4 * f], acc);
                cur = rr[j];
                acc = make_float4(0.f, 0.f, 0.f, 0.f);
            }
            acc.x = fmaf(w[j], v[j].x, acc.x);
            acc.y = fmaf(w[j], v[j].y, acc.y);
            acc.z = fmaf(w[j], v[j].z, acc.z);
            acc.w = fmaf(w[j], v[j].w, acc.w);
        }
    }
    for (; i < cnt; i++) {
        int   r = s_row[g][i];
        uint2 cw = s_cw[g][i];
        float w  = __uint_as_float(cw.y);
        float4 v = __ldg(&src4[(size_t)cw.x * T]);
        if (r != cur) {
            if (cur >= 0) red4(&dst[(size_t)cur * F + 4 * f], acc);
            cur = r;
            acc = make_float4(0.f, 0.f, 0.f, 0.f);
        }
        acc.x = fmaf(w, v.x, acc.x);
        acc.y = fmaf(w, v.y, acc.y);
        acc.z = fmaf(w, v.z, acc.z);
        acc.w = fmaf(w, v.w, acc.w);
    }
    if (cur >= 0) red4(&dst[(size_t)cur * F + 4 * f], acc);
}

// ===========================================================================
extern "C" void kernel_launch(void* const* d_in, const int* in_sizes, int n_in,
                              void* d_out, int out_size)
{
    const float* x   = (const float*)d_in[0];
    const float* w1  = (const float*)d_in[1];
    const float* b1  = (const float*)d_in[2];
    const float* w2  = (const float*)d_in[3];
    const float* b2  = (const float*)d_in[4];
    const float* ew  = (const float*)d_in[5];
    const int*   row = (const int*)d_in[6];
    const int*   col = (const int*)d_in[7];

    const int nhid  = in_sizes[2];            // 256
    const int nout  = in_sizes[4];            // 64
    const int nfeat = in_sizes[1] / nhid;     // 512
    const int n     = in_sizes[0] / nfeat;    // 50000
    const int E     = in_sizes[5];            // 800000

    void *p1, *p2, *p3, *p4, *p5;
    cudaGetSymbolAddress(&p1, g_h1);
    cudaGetSymbolAddress(&p2, g_h2);
    cudaGetSymbolAddress(&p3, g_h3);
    cudaGetSymbolAddress(&p4, g_w1t);
    cudaGetSymbolAddress(&p5, g_w2t);
    float* h1  = (float*)p1;
    float* h2  = (float*)p2;
    float* h3  = (float*)p3;
    float* w1t = (float*)p4;
    float* w2t = (float*)p5;
    float* out = (float*)d_out;

    const int tilesM = (n + 127) / 128;                   // 391

    // 0) both W transposes (+ tf32 RN rounding), single launch
    {
        int sz1 = nfeat * nhid, sz2 = nhid * nout;
        transpose_round2<<<(sz1 + sz2 + 255) / 256, 256>>>(
            w1, w1t, w2, w2t, sz1, nhid, nfeat, sz2, nout, nhid);
    }

    // 1) h1 = x @ W1   (4-warp 64x64-tile mma; A rna-rounded in registers)
    {
        dim3 grid(nhid / 128, tilesM);
        gemm_mma_big<1><<<grid, 128>>>(x, w1t, h1, n, nfeat, nhid);
    }

    // 2) h2 = b1 + scatter(edge_w * h1[col]) into row
    {
        int total4 = n * nhid / 4;
        init_bias4<<<(total4 + 255) / 256, 256>>>(
            (float4*)h2, (const float4*)b1, total4, nhid / 4 - 1);
        // F=256: T=64, G=4, EPG=128 -> 512 edges/block, grid=1563 (fills occ slots)
        spmm_scatter4<256, 128, 4><<<(E + 511) / 512, 256>>>(h1, ew, row, col, h2, E);
    }

    // 3) h3 = relu(h2) @ W2   (relu + rna fused into A-register path)
    {
        dim3 grid(nout / 64, tilesM);
        gemm_mma<64, 2, 2><<<grid, 256>>>(h2, w2t, h3, n, nhid, nout);
    }

    // 4) out = b2 + scatter(edge_w * h3[col])
    {
        int total4 = n * nout / 4;
        init_bias4<<<(total4 + 255) / 256, 256>>>(
            (float4*)out, (const float4*)b2, total4, nout / 4 - 1);
        // F=64: T=16, G=16, EPG=64 -> 1024 edges/block, grid=782
        spmm_scatter4<64, 64, 16><<<(E + 1023) / 1024, 256>>>(h3, ew, row, col, out, E);
    }
}

// round 8
// speedup vs baseline: 1.4087x; 1.4087x over previous
#include <cuda_runtime.h>
#include <cstdint>

// Problem constants (fixed by dataset)
#define MAXN   50000
#define NFEAT  512
#define FHID   256
#define FOUT   64

// Scratch (device globals: allocation-free per harness rules)
__device__ float g_h1 [MAXN * FHID];    // x @ W1
__device__ float g_h2 [MAXN * FHID];    // spmm(h1) + b1  (relu+rna applied on read in GEMM2)
__device__ float g_h3 [MAXN * FOUT];    // relu(h2) @ W2
__device__ float g_w1t[FHID * NFEAT];   // W1^T, tf32-rounded
__device__ float g_w2t[FOUT * FHID];    // W2^T, tf32-rounded

// ===========================================================================
// helpers
// ===========================================================================
__device__ __forceinline__ uint32_t smem_u32(const void* p) {
    uint32_t a;
    asm("{ .reg .u64 t; cvta.to.shared.u64 t, %1; cvt.u32.u64 %0, t; }"
        : "=r"(a) : "l"(p));
    return a;
}
__device__ __forceinline__ float rna_tf32(float f) {
    uint32_t u;
    asm("cvt.rna.tf32.f32 %0, %1;" : "=r"(u) : "f"(f));
    return __uint_as_float(u);
}
__device__ __forceinline__ void cp16(uint32_t dst, const void* src) {
    asm volatile("cp.async.cg.shared.global [%0], [%1], 16;"
                 :: "r"(dst), "l"(src) : "memory");
}
#define CP_COMMIT() asm volatile("cp.async.commit_group;" ::: "memory")
#define CP_WAIT0()  asm volatile("cp.async.wait_group 0;" ::: "memory")

// vectorized global reduction (PTX 8.1+, sm_90+ base feature)
__device__ __forceinline__ void red4(float* addr, float4 v) {
    asm volatile("red.global.add.v4.f32 [%0], {%1,%2,%3,%4};"
                 :: "l"(addr), "f"(v.x), "f"(v.y), "f"(v.z), "f"(v.w) : "memory");
}

// mma.sync m16n8k8 tf32 (base PTX, works on compute_103 target)
__device__ __forceinline__ void mma8(float* d, const uint32_t* a, const uint32_t* b) {
    asm volatile(
        "mma.sync.aligned.m16n8k8.row.col.f32.tf32.tf32.f32 "
        "{%0,%1,%2,%3}, {%4,%5,%6,%7}, {%8,%9}, {%0,%1,%2,%3};"
        : "+f"(d[0]), "+f"(d[1]), "+f"(d[2]), "+f"(d[3])
        : "r"(a[0]), "r"(a[1]), "r"(a[2]), "r"(a[3]), "r"(b[0]), "r"(b[1]));
}

// ===========================================================================
// Big-warp-tile tf32 GEMM (GEMM1):  C[M,Ntot] = op(A)[M,K] @ Bt[Ntot,K]^T
//   BM=128, BN=128, BK=16; 128 threads = 4 warps (2M x 2N); warp tile 64x64
//   -> SMEM crossbar traffic 32KB/chunk (proven win in R6).
// ===========================================================================
template<int AMODE>
__global__ void __launch_bounds__(128)
gemm_mma_big(const float* __restrict__ A, const float* __restrict__ Bt,
             float* __restrict__ C, int M, int K, int Ntot)
{
    constexpr int BM = 128, BN = 128, BK = 16, LDS = 20;
    __shared__ float As[2][BM * LDS];
    __shared__ float Bs[2][BN * LDS];

    const int tid  = threadIdx.x;
    const int lane = tid & 31, wid = tid >> 5;
    const int g    = lane >> 2, tig = lane & 3;
    const int wm0  = (wid >> 1) * 64;
    const int wn0  = (wid & 1) * 64;
    const int blockM = blockIdx.y * BM;
    const int blockN = blockIdx.x * BN;

    const int arow = tid >> 2;                   // 0..31 (A rows: arow + 32i)
    const int aq   = tid & 3;

    float acc[4][8][4];
    #pragma unroll
    for (int mt = 0; mt < 4; mt++)
        #pragma unroll
        for (int nt = 0; nt < 8; nt++)
            #pragma unroll
            for (int i = 0; i < 4; i++) acc[mt][nt][i] = 0.f;

    auto ldgA = [&](int c, float4* av) {
        const int k0 = c * BK;
        #pragma unroll
        for (int i = 0; i < 4; i++) {
            int r = blockM + arow + i * 32;
            if (r < M)
                av[i] = *reinterpret_cast<const float4*>(&A[(size_t)r * K + k0 + aq * 4]);
            else
                av[i] = make_float4(0.f, 0.f, 0.f, 0.f);
        }
    };
    auto stsA = [&](int buf, float4* av) {
        #pragma unroll
        for (int i = 0; i < 4; i++) {
            float4 v = av[i];
            if (AMODE == 2) {
                v.x = fmaxf(v.x, 0.f); v.y = fmaxf(v.y, 0.f);
                v.z = fmaxf(v.z, 0.f); v.w = fmaxf(v.w, 0.f);
            }
            if (AMODE >= 1) {
                v.x = rna_tf32(v.x); v.y = rna_tf32(v.y);
                v.z = rna_tf32(v.z); v.w = rna_tf32(v.w);
            }
            *reinterpret_cast<float4*>(&As[buf][(arow + i * 32) * LDS + aq * 4]) = v;
        }
    };
    auto cpB = [&](int c, int buf) {
        const int k0 = c * BK;
        #pragma unroll
        for (int i = 0; i < 4; i++) {
            int u = tid + i * 128;
            int r = u >> 2, q = u & 3;
            cp16(smem_u32(&Bs[buf][r * LDS + q * 4]),
                 &Bt[(size_t)(blockN + r) * K + k0 + q * 4]);
        }
        CP_COMMIT();
    };
    auto compute = [&](int buf) {
        #pragma unroll
        for (int ks = 0; ks < 2; ks++) {
            uint32_t a[4][4], b[8][2];
            #pragma unroll
            for (int mt = 0; mt < 4; mt++) {
                const float* p0 = &As[buf][(wm0 + mt * 16 + g) * LDS + ks * 8];
                const float* p1 = p0 + 8 * LDS;
                a[mt][0] = __float_as_uint(p0[tig]);
                a[mt][2] = __float_as_uint(p0[tig + 4]);
                a[mt][1] = __float_as_uint(p1[tig]);
                a[mt][3] = __float_as_uint(p1[tig + 4]);
            }
            #pragma unroll
            for (int nt = 0; nt < 8; nt++) {
                const float* pb = &Bs[buf][(wn0 + nt * 8 + g) * LDS + ks * 8];
                b[nt][0] = __float_as_uint(pb[tig]);
                b[nt][1] = __float_as_uint(pb[tig + 4]);
            }
            #pragma unroll
            for (int mt = 0; mt < 4; mt++)
                #pragma unroll
                for (int nt = 0; nt < 8; nt++)
                    mma8(acc[mt][nt], a[mt], b[nt]);
        }
    };

    // prologue
    {
        float4 av[4];
        ldgA(0, av);
        cpB(0, 0);
        stsA(0, av);
        CP_WAIT0();
        __syncthreads();
    }

    const int NC = K / BK;
    for (int c = 0; c < NC; c++) {
        float4 av[4];
        const bool more = (c + 1 < NC);
        if (more) {
            ldgA(c + 1, av);
            cpB(c + 1, (c + 1) & 1);
        }
        compute(c & 1);
        if (more) {
            stsA((c + 1) & 1, av);
            CP_WAIT0();
            __syncthreads();
        }
    }

    // epilogue
    #pragma unroll
    for (int mt = 0; mt < 4; mt++) {
        int r0 = blockM + wm0 + mt * 16 + g;
        int r1 = r0 + 8;
        #pragma unroll
        for (int nt = 0; nt < 8; nt++) {
            int cb = blockN + wn0 + nt * 8 + 2 * tig;
            if (r0 < M)
                *reinterpret_cast<float2*>(&C[(size_t)r0 * Ntot + cb]) =
                    make_float2(acc[mt][nt][0], acc[mt][nt][1]);
            if (r1 < M)
                *reinterpret_cast<float2*>(&C[(size_t)r1 * Ntot + cb]) =
                    make_float2(acc[mt][nt][2], acc[mt][nt][3]);
        }
    }
}

// ===========================================================================
// 8-warp tf32 GEMM (GEMM2, BN=64):  C = op(A) @ Bt^T
// ===========================================================================
template<int BN, int WNT, int AMODE>
__global__ void __launch_bounds__(256)
gemm_mma(const float* __restrict__ A, const float* __restrict__ Bt,
         float* __restrict__ C, int M, int K, int Ntot)
{
    constexpr int BM = 128, BK = 16, LDS = 20;
    constexpr int NBI = (BN * BK / 4) / 256;
    __shared__ float As[2][BM * LDS];
    __shared__ float Bs[2][BN * LDS];

    const int tid  = threadIdx.x;
    const int lane = tid & 31, wid = tid >> 5;
    const int g    = lane >> 2, tig = lane & 3;
    const int wm0  = (wid >> 2) * 64;
    const int wn0  = (wid & 3) * (BN / 4);
    const int blockM = blockIdx.y * BM;
    const int blockN = blockIdx.x * BN;

    const int arow = tid >> 2;
    const int aq   = tid & 3;

    float acc[4][WNT][4];
    #pragma unroll
    for (int mt = 0; mt < 4; mt++)
        #pragma unroll
        for (int nt = 0; nt < WNT; nt++)
            #pragma unroll
            for (int i = 0; i < 4; i++) acc[mt][nt][i] = 0.f;

    auto ldgA = [&](int c, float4* av) {
        const int k0 = c * BK;
        #pragma unroll
        for (int i = 0; i < 2; i++) {
            int r = blockM + arow + i * 64;
            if (r < M)
                av[i] = *reinterpret_cast<const float4*>(&A[(size_t)r * K + k0 + aq * 4]);
            else
                av[i] = make_float4(0.f, 0.f, 0.f, 0.f);
        }
    };
    auto stsA = [&](int buf, float4* av) {
        #pragma unroll
        for (int i = 0; i < 2; i++) {
            float4 v = av[i];
            if (AMODE == 2) {
                v.x = fmaxf(v.x, 0.f); v.y = fmaxf(v.y, 0.f);
                v.z = fmaxf(v.z, 0.f); v.w = fmaxf(v.w, 0.f);
            }
            if (AMODE >= 1) {
                v.x = rna_tf32(v.x); v.y = rna_tf32(v.y);
                v.z = rna_tf32(v.z); v.w = rna_tf32(v.w);
            }
            *reinterpret_cast<float4*>(&As[buf][(arow + i * 64) * LDS + aq * 4]) = v;
        }
    };
    auto cpB = [&](int c, int buf) {
        const int k0 = c * BK;
        #pragma unroll
        for (int i = 0; i < NBI; i++) {
            int u = tid + i * 256;
            int r = u >> 2, q = u & 3;
            cp16(smem_u32(&Bs[buf][r * LDS + q * 4]),
                 &Bt[(size_t)(blockN + r) * K + k0 + q * 4]);
        }
        CP_COMMIT();
    };
    auto compute = [&](int buf) {
        #pragma unroll
        for (int ks = 0; ks < 2; ks++) {
            uint32_t a[4][4], b[WNT][2];
            #pragma unroll
            for (int mt = 0; mt < 4; mt++) {
                const float* p0 = &As[buf][(wm0 + mt * 16 + g) * LDS + ks * 8];
                const float* p1 = p0 + 8 * LDS;
                a[mt][0] = __float_as_uint(p0[tig]);
                a[mt][2] = __float_as_uint(p0[tig + 4]);
                a[mt][1] = __float_as_uint(p1[tig]);
                a[mt][3] = __float_as_uint(p1[tig + 4]);
            }
            #pragma unroll
            for (int nt = 0; nt < WNT; nt++) {
                const float* pb = &Bs[buf][(wn0 + nt * 8 + g) * LDS + ks * 8];
                b[nt][0] = __float_as_uint(pb[tig]);
                b[nt][1] = __float_as_uint(pb[tig + 4]);
            }
            #pragma unroll
            for (int mt = 0; mt < 4; mt++)
                #pragma unroll
                for (int nt = 0; nt < WNT; nt++)
                    mma8(acc[mt][nt], a[mt], b[nt]);
        }
    };

    {
        float4 av[2];
        ldgA(0, av);
        cpB(0, 0);
        stsA(0, av);
        CP_WAIT0();
        __syncthreads();
    }

    const int NC = K / BK;
    for (int c = 0; c < NC; c++) {
        float4 av[2];
        const bool more = (c + 1 < NC);
        if (more) {
            ldgA(c + 1, av);
            cpB(c + 1, (c + 1) & 1);
        }
        compute(c & 1);
        if (more) {
            stsA((c + 1) & 1, av);
            CP_WAIT0();
            __syncthreads();
        }
    }

    #pragma unroll
    for (int mt = 0; mt < 4; mt++) {
        int r0 = blockM + wm0 + mt * 16 + g;
        int r1 = r0 + 8;
        #pragma unroll
        for (int nt = 0; nt < WNT; nt++) {
            int cb = blockN + wn0 + nt * 8 + 2 * tig;
            if (r0 < M)
                *reinterpret_cast<float2*>(&C[(size_t)r0 * Ntot + cb]) =
                    make_float2(acc[mt][nt][0], acc[mt][nt][1]);
            if (r1 < M)
                *reinterpret_cast<float2*>(&C[(size_t)r1 * Ntot + cb]) =
                    make_float2(acc[mt][nt][2], acc[mt][nt][3]);
        }
    }
}

// ===========================================================================
// Elementwise kernels
// ===========================================================================
__global__ void transpose_round2(const float* __restrict__ w1, float* __restrict__ w1t,
                                 const float* __restrict__ w2, float* __restrict__ w2t,
                                 int sz1, int n1, int k1, int sz2, int n2, int k2)
{
    int i = blockIdx.x * blockDim.x + threadIdx.x;
    if (i < sz1) {
        int k = i / n1, n = i % n1;
        w1t[(size_t)n * k1 + k] = rna_tf32(w1[i]);
    } else if (i < sz1 + sz2) {
        int j = i - sz1;
        int k = j / n2, n = j % n2;
        w2t[(size_t)n * k2 + k] = rna_tf32(w2[j]);
    }
}

__global__ void init_bias4(float4* __restrict__ dst, const float4* __restrict__ bias,
                           int total4, int fmask4)
{
    int i = blockIdx.x * blockDim.x + threadIdx.x;
    if (i < total4) dst[i] = bias[i & fmask4];
}

// ---------------------------------------------------------------------------
// SpMM scatter (float4 lanes) — R5 PROVEN CONFIG, verbatim.
// dst[row[e]] += edge_w[e] * src[col[e]], row sorted ascending.
// T = F/4 threads per edge-group, G groups per block, batched-4 LDG.128.
// ---------------------------------------------------------------------------
template<int F, int EPG, int G>
__global__ void __launch_bounds__((F / 4) * G)
spmm_scatter4(const float* __restrict__ src, const float* __restrict__ ew,
              const int* __restrict__ row, const int* __restrict__ col,
              float* __restrict__ dst, int E)
{
    constexpr int T = F / 4;
    __shared__ int   s_row[G][EPG];
    __shared__ uint2 s_cw[G][EPG];     // {col, edge_w bits}

    const int g = threadIdx.x / T;
    const int f = threadIdx.x % T;     // covers floats [4f, 4f+4)
    const long base = ((long)blockIdx.x * G + g) * EPG;

    long rem = (long)E - base;
    const int cnt = rem <= 0 ? 0 : (rem < EPG ? (int)rem : EPG);

    for (int i = f; i < cnt; i += T) {
        long e = base + i;
        s_row[g][i] = row[e];
        s_cw[g][i]  = make_uint2((unsigned)col[e], __float_as_uint(ew[e]));
    }
    __syncthreads();

    const float4* src4 = reinterpret_cast<const float4*>(src) + f;
    float4 acc = make_float4(0.f, 0.f, 0.f, 0.f);
    int    cur = -1;

    int i = 0;
    const int full = cnt & ~3;
    for (; i < full; i += 4) {
        int rr[4]; float w[4]; float4 v[4];
        #pragma unroll
        for (int j = 0; j < 4; j++) {              // 4 LDG.128 in flight
            rr[j] = s_row[g][i + j];
            uint2 cw = s_cw[g][i + j];
            w[j] = __uint_as_float(cw.y);
            v[j] = __ldg(&src4[(size_t)cw.x * T]);
        }
        #pragma unroll
        for (int j = 0; j < 4; j++) {              // register-only scan
            if (rr[j] != cur) {
                if (cur >= 0) red4(&dst[(size_t)cur * F + 4 * f], acc);
                cur = rr[j];
                acc = make_float4(0.f, 0.f, 0.f, 0.f);
            }
            acc.x = fmaf(w[j], v[j].x, acc.x);
            acc.y = fmaf(w[j], v[j].y, acc.y);
            acc.z = fmaf(w[j], v[j].z, acc.z);
            acc.w = fmaf(w[j], v[j].w, acc.w);
        }
    }
    for (; i < cnt; i++) {
        int   r = s_row[g][i];
        uint2 cw = s_cw[g][i];
        float w  = __uint_as_float(cw.y);
        float4 v = __ldg(&src4[(size_t)cw.x * T]);
        if (r != cur) {
            if (cur >= 0) red4(&dst[(size_t)cur * F + 4 * f], acc);
            cur = r;
            acc = make_float4(0.f, 0.f, 0.f, 0.f);
        }
        acc.x = fmaf(w, v.x, acc.x);
        acc.y = fmaf(w, v.y, acc.y);
        acc.z = fmaf(w, v.z, acc.z);
        acc.w = fmaf(w, v.w, acc.w);
    }
    if (cur >= 0) red4(&dst[(size_t)cur * F + 4 * f], acc);
}

// ===========================================================================
extern "C" void kernel_launch(void* const* d_in, const int* in_sizes, int n_in,
                              void* d_out, int out_size)
{
    const float* x   = (const float*)d_in[0];
    const float* w1  = (const float*)d_in[1];
    const float* b1  = (const float*)d_in[2];
    const float* w2  = (const float*)d_in[3];
    const float* b2  = (const float*)d_in[4];
    const float* ew  = (const float*)d_in[5];
    const int*   row = (const int*)d_in[6];
    const int*   col = (const int*)d_in[7];

    const int nhid  = in_sizes[2];            // 256
    const int nout  = in_sizes[4];            // 64
    const int nfeat = in_sizes[1] / nhid;     // 512
    const int n     = in_sizes[0] / nfeat;    // 50000
    const int E     = in_sizes[5];            // 800000

    void *p1, *p2, *p3, *p4, *p5;
    cudaGetSymbolAddress(&p1, g_h1);
    cudaGetSymbolAddress(&p2, g_h2);
    cudaGetSymbolAddress(&p3, g_h3);
    cudaGetSymbolAddress(&p4, g_w1t);
    cudaGetSymbolAddress(&p5, g_w2t);
    float* h1  = (float*)p1;
    float* h2  = (float*)p2;
    float* h3  = (float*)p3;
    float* w1t = (float*)p4;
    float* w2t = (float*)p5;
    float* out = (float*)d_out;

    const int tilesM = (n + 127) / 128;                   // 391

    // 0) both W transposes (+ tf32 RN rounding), single launch
    {
        int sz1 = nfeat * nhid, sz2 = nhid * nout;
        transpose_round2<<<(sz1 + sz2 + 255) / 256, 256>>>(
            w1, w1t, w2, w2t, sz1, nhid, nfeat, sz2, nout, nhid);
    }

    // 1) h1 = x @ W1   (4-warp 64x64-tile mma; A rna-rounded in registers)
    {
        dim3 grid(nhid / 128, tilesM);
        gemm_mma_big<1><<<grid, 128>>>(x, w1t, h1, n, nfeat, nhid);
    }

    // 2) h2 = b1 + scatter(edge_w * h1[col]) into row   [R5 proven config]
    {
        int total4 = n * nhid / 4;
        init_bias4<<<(total4 + 255) / 256, 256>>>(
            (float4*)h2, (const float4*)b1, total4, nhid / 4 - 1);
        // F=256: T=64, G=4, EPG=256 -> 1024 edges/block, grid=782
        spmm_scatter4<256, 256, 4><<<(E + 1023) / 1024, 256>>>(h1, ew, row, col, h2, E);
    }

    // 3) h3 = relu(h2) @ W2   (relu + rna fused into A-register path)
    {
        dim3 grid(nout / 64, tilesM);
        gemm_mma<64, 2, 2><<<grid, 256>>>(h2, w2t, h3, n, nhid, nout);
    }

    // 4) out = b2 + scatter(edge_w * h3[col])   [R5 proven config]
    {
        int total4 = n * nout / 4;
        init_bias4<<<(total4 + 255) / 256, 256>>>(
            (float4*)out, (const float4*)b2, total4, nout / 4 - 1);
        // F=64: T=16, G=16, EPG=128 -> 2048 edges/block, grid=391
        spmm_scatter4<64, 128, 16><<<(E + 2047) / 2048, 256>>>(h3, ew, row, col, out, E);
    }
}

// round 9
// speedup vs baseline: 1.6057x; 1.1398x over previous
#include <cuda_runtime.h>
#include <cuda_fp16.h>
#include <cstdint>

// Problem constants (fixed by dataset)
#define MAXN   50000
#define NFEAT  512
#define FHID   256
#define FOUT   64

// Scratch (device globals: allocation-free per harness rules)
__device__ float  g_h1 [MAXN * FHID];    // x @ W1
__device__ float  g_h2 [MAXN * FHID];    // spmm(h1) + b1
__device__ float  g_h3 [MAXN * FOUT];    // relu(h2) @ W2
__device__ __half g_w1t[FHID * NFEAT];   // W1^T, fp16
__device__ __half g_w2t[FOUT * FHID];    // W2^T, fp16

// ===========================================================================
// helpers
// ===========================================================================
__device__ __forceinline__ uint32_t smem_u32(const void* p) {
    uint32_t a;
    asm("{ .reg .u64 t; cvta.to.shared.u64 t, %1; cvt.u32.u64 %0, t; }"
        : "=r"(a) : "l"(p));
    return a;
}
__device__ __forceinline__ void cp16(uint32_t dst, const void* src) {
    asm volatile("cp.async.cg.shared.global [%0], [%1], 16;"
                 :: "r"(dst), "l"(src) : "memory");
}
#define CP_COMMIT() asm volatile("cp.async.commit_group;" ::: "memory")
#define CP_WAIT0()  asm volatile("cp.async.wait_group 0;" ::: "memory")

// vectorized global reduction (PTX 8.1+, sm_90+ base feature)
__device__ __forceinline__ void red4(float* addr, float4 v) {
    asm volatile("red.global.add.v4.f32 [%0], {%1,%2,%3,%4};"
                 :: "l"(addr), "f"(v.x), "f"(v.y), "f"(v.z), "f"(v.w) : "memory");
}

// mma.sync m16n8k16 fp16 inputs, fp32 accum (base PTX, sm_80+)
__device__ __forceinline__ void mma16(float* d, const uint32_t* a, const uint32_t* b) {
    asm volatile(
        "mma.sync.aligned.m16n8k16.row.col.f32.f16.f16.f32 "
        "{%0,%1,%2,%3}, {%4,%5,%6,%7}, {%8,%9}, {%0,%1,%2,%3};"
        : "+f"(d[0]), "+f"(d[1]), "+f"(d[2]), "+f"(d[3])
        : "r"(a[0]), "r"(a[1]), "r"(a[2]), "r"(a[3]), "r"(b[0]), "r"(b[1]));
}

// pack 2 floats -> half2 bits (RN)
__device__ __forceinline__ uint32_t f2h2(float x, float y) {
    __half2 h = __floats2half2_rn(x, y);
    return *reinterpret_cast<uint32_t*>(&h);
}

// ===========================================================================
// Big-warp-tile fp16 GEMM (GEMM1):  C[M,Ntot] = op(A)[M,K] @ Bt[Ntot,K]^T
//   BM=128, BN=128, BK=16; 128 threads = 4 warps (2M x 2N); warp tile 64x64.
//   A fp32 in gmem, converted to fp16 (RN) in register staging; Bt fp16.
//   SMEM row stride 24 halves -> conflict-free LDS.32 fragment loads.
// ===========================================================================
template<int AMODE>   // 1 = cvt only, 2 = relu + cvt
__global__ void __launch_bounds__(128)
gemm_mma_big(const float* __restrict__ A, const __half* __restrict__ Bt,
             float* __restrict__ C, int M, int K, int Ntot)
{
    constexpr int BM = 128, BN = 128, BK = 16, LDSH = 24;
    __shared__ __half As[2][BM * LDSH];
    __shared__ __half Bs[2][BN * LDSH];

    const int tid  = threadIdx.x;
    const int lane = tid & 31, wid = tid >> 5;
    const int g    = lane >> 2, tig = lane & 3;
    const int wm0  = (wid >> 1) * 64;
    const int wn0  = (wid & 1) * 64;
    const int blockM = blockIdx.y * BM;
    const int blockN = blockIdx.x * BN;

    const int arow = tid >> 2;                   // 0..31 (A rows: arow + 32i)
    const int aq   = tid & 3;                    // float4 slot within 16-col row

    float acc[4][8][4];
    #pragma unroll
    for (int mt = 0; mt < 4; mt++)
        #pragma unroll
        for (int nt = 0; nt < 8; nt++)
            #pragma unroll
            for (int i = 0; i < 4; i++) acc[mt][nt][i] = 0.f;

    auto ldgA = [&](int c, float4* av) {
        const int k0 = c * BK;
        #pragma unroll
        for (int i = 0; i < 4; i++) {
            int r = blockM + arow + i * 32;
            if (r < M)
                av[i] = *reinterpret_cast<const float4*>(&A[(size_t)r * K + k0 + aq * 4]);
            else
                av[i] = make_float4(0.f, 0.f, 0.f, 0.f);
        }
    };
    auto stsA = [&](int buf, float4* av) {
        #pragma unroll
        for (int i = 0; i < 4; i++) {
            float4 v = av[i];
            if (AMODE == 2) {
                v.x = fmaxf(v.x, 0.f); v.y = fmaxf(v.y, 0.f);
                v.z = fmaxf(v.z, 0.f); v.w = fmaxf(v.w, 0.f);
            }
            uint2 h = make_uint2(f2h2(v.x, v.y), f2h2(v.z, v.w));
            *reinterpret_cast<uint2*>(&As[buf][(arow + i * 32) * LDSH + aq * 4]) = h;
        }
    };
    auto cpB = [&](int c, int buf) {
        const int k0 = c * BK;
        #pragma unroll
        for (int i = 0; i < 2; i++) {            // BN rows x 2 x 16B chunks
            int u = tid + i * 128;
            int r = u >> 1, q = u & 1;
            cp16(smem_u32(&Bs[buf][r * LDSH + q * 8]),
                 &Bt[(size_t)(blockN + r) * K + k0 + q * 8]);
        }
        CP_COMMIT();
    };
    auto compute = [&](int buf) {
        uint32_t a[4][4], b[8][2];
        #pragma unroll
        for (int mt = 0; mt < 4; mt++) {
            const __half* p = &As[buf][(wm0 + mt * 16 + g) * LDSH + 2 * tig];
            a[mt][0] = *reinterpret_cast<const uint32_t*>(p);
            a[mt][1] = *reinterpret_cast<const uint32_t*>(p + 8 * LDSH);
            a[mt][2] = *reinterpret_cast<const uint32_t*>(p + 8);
            a[mt][3] = *reinterpret_cast<const uint32_t*>(p + 8 * LDSH + 8);
        }
        #pragma unroll
        for (int nt = 0; nt < 8; nt++) {
            const __half* pb = &Bs[buf][(wn0 + nt * 8 + g) * LDSH + 2 * tig];
            b[nt][0] = *reinterpret_cast<const uint32_t*>(pb);
            b[nt][1] = *reinterpret_cast<const uint32_t*>(pb + 8);
        }
        #pragma unroll
        for (int mt = 0; mt < 4; mt++)
            #pragma unroll
            for (int nt = 0; nt < 8; nt++)
                mma16(acc[mt][nt], a[mt], b[nt]);
    };

    // prologue
    {
        float4 av[4];
        ldgA(0, av);
        cpB(0, 0);
        stsA(0, av);
        CP_WAIT0();
        __syncthreads();
    }

    const int NC = K / BK;
    for (int c = 0; c < NC; c++) {
        float4 av[4];
        const bool more = (c + 1 < NC);
        if (more) {
            ldgA(c + 1, av);
            cpB(c + 1, (c + 1) & 1);
        }
        compute(c & 1);
        if (more) {
            stsA((c + 1) & 1, av);
            CP_WAIT0();
            __syncthreads();
        }
    }

    // epilogue
    #pragma unroll
    for (int mt = 0; mt < 4; mt++) {
        int r0 = blockM + wm0 + mt * 16 + g;
        int r1 = r0 + 8;
        #pragma unroll
        for (int nt = 0; nt < 8; nt++) {
            int cb = blockN + wn0 + nt * 8 + 2 * tig;
            if (r0 < M)
                *reinterpret_cast<float2*>(&C[(size_t)r0 * Ntot + cb]) =
                    make_float2(acc[mt][nt][0], acc[mt][nt][1]);
            if (r1 < M)
                *reinterpret_cast<float2*>(&C[(size_t)r1 * Ntot + cb]) =
                    make_float2(acc[mt][nt][2], acc[mt][nt][3]);
        }
    }
}

// ===========================================================================
// 8-warp fp16 GEMM (GEMM2, BN=64):  C = op(A) @ Bt^T ; warp tile 64x16
// ===========================================================================
template<int BN, int WNT, int AMODE>
__global__ void __launch_bounds__(256)
gemm_mma(const float* __restrict__ A, const __half* __restrict__ Bt,
         float* __restrict__ C, int M, int K, int Ntot)
{
    constexpr int BM = 128, BK = 16, LDSH = 24;
    __shared__ __half As[2][BM * LDSH];
    __shared__ __half Bs[2][BN * LDSH];

    const int tid  = threadIdx.x;
    const int lane = tid & 31, wid = tid >> 5;
    const int g    = lane >> 2, tig = lane & 3;
    const int wm0  = (wid >> 2) * 64;
    const int wn0  = (wid & 3) * (BN / 4);
    const int blockM = blockIdx.y * BM;
    const int blockN = blockIdx.x * BN;

    const int arow = tid >> 2;                   // 0..63
    const int aq   = tid & 3;

    float acc[4][WNT][4];
    #pragma unroll
    for (int mt = 0; mt < 4; mt++)
        #pragma unroll
        for (int nt = 0; nt < WNT; nt++)
            #pragma unroll
            for (int i = 0; i < 4; i++) acc[mt][nt][i] = 0.f;

    auto ldgA = [&](int c, float4* av) {
        const int k0 = c * BK;
        #pragma unroll
        for (int i = 0; i < 2; i++) {
            int r = blockM + arow + i * 64;
            if (r < M)
                av[i] = *reinterpret_cast<const float4*>(&A[(size_t)r * K + k0 + aq * 4]);
            else
                av[i] = make_float4(0.f, 0.f, 0.f, 0.f);
        }
    };
    auto stsA = [&](int buf, float4* av) {
        #pragma unroll
        for (int i = 0; i < 2; i++) {
            float4 v = av[i];
            if (AMODE == 2) {
                v.x = fmaxf(v.x, 0.f); v.y = fmaxf(v.y, 0.f);
                v.z = fmaxf(v.z, 0.f); v.w = fmaxf(v.w, 0.f);
            }
            uint2 h = make_uint2(f2h2(v.x, v.y), f2h2(v.z, v.w));
            *reinterpret_cast<uint2*>(&As[buf][(arow + i * 64) * LDSH + aq * 4]) = h;
        }
    };
    auto cpB = [&](int c, int buf) {
        const int k0 = c * BK;
        int u = tid;                              // BN*2 chunks (128 for BN=64)
        if (u < BN * 2) {
            int r = u >> 1, q = u & 1;
            cp16(smem_u32(&Bs[buf][r * LDSH + q * 8]),
                 &Bt[(size_t)(blockN + r) * K + k0 + q * 8]);
        }
        CP_COMMIT();
    };
    auto compute = [&](int buf) {
        uint32_t a[4][4], b[WNT][2];
        #pragma unroll
        for (int mt = 0; mt < 4; mt++) {
            const __half* p = &As[buf][(wm0 + mt * 16 + g) * LDSH + 2 * tig];
            a[mt][0] = *reinterpret_cast<const uint32_t*>(p);
            a[mt][1] = *reinterpret_cast<const uint32_t*>(p + 8 * LDSH);
            a[mt][2] = *reinterpret_cast<const uint32_t*>(p + 8);
            a[mt][3] = *reinterpret_cast<const uint32_t*>(p + 8 * LDSH + 8);
        }
        #pragma unroll
        for (int nt = 0; nt < WNT; nt++) {
            const __half* pb = &Bs[buf][(wn0 + nt * 8 + g) * LDSH + 2 * tig];
            b[nt][0] = *reinterpret_cast<const uint32_t*>(pb);
            b[nt][1] = *reinterpret_cast<const uint32_t*>(pb + 8);
        }
        #pragma unroll
        for (int mt = 0; mt < 4; mt++)
            #pragma unroll
            for (int nt = 0; nt < WNT; nt++)
                mma16(acc[mt][nt], a[mt], b[nt]);
    };

    {
        float4 av[2];
        ldgA(0, av);
        cpB(0, 0);
        stsA(0, av);
        CP_WAIT0();
        __syncthreads();
    }

    const int NC = K / BK;
    for (int c = 0; c < NC; c++) {
        float4 av[2];
        const bool more = (c + 1 < NC);
        if (more) {
            ldgA(c + 1, av);
            cpB(c + 1, (c + 1) & 1);
        }
        compute(c & 1);
        if (more) {
            stsA((c + 1) & 1, av);
            CP_WAIT0();
            __syncthreads();
        }
    }

    #pragma unroll
    for (int mt = 0; mt < 4; mt++) {
        int r0 = blockM + wm0 + mt * 16 + g;
        int r1 = r0 + 8;
        #pragma unroll
        for (int nt = 0; nt < WNT; nt++) {
            int cb = blockN + wn0 + nt * 8 + 2 * tig;
            if (r0 < M)
                *reinterpret_cast<float2*>(&C[(size_t)r0 * Ntot + cb]) =
                    make_float2(acc[mt][nt][0], acc[mt][nt][1]);
            if (r1 < M)
                *reinterpret_cast<float2*>(&C[(size_t)r1 * Ntot + cb]) =
                    make_float2(acc[mt][nt][2], acc[mt][nt][3]);
        }
    }
}

// ===========================================================================
// Elementwise kernels
// ===========================================================================
__global__ void transpose_round2(const float* __restrict__ w1, __half* __restrict__ w1t,
                                 const float* __restrict__ w2, __half* __restrict__ w2t,
                                 int sz1, int n1, int k1, int sz2, int n2, int k2)
{
    int i = blockIdx.x * blockDim.x + threadIdx.x;
    if (i < sz1) {
        int k = i / n1, n = i % n1;
        w1t[(size_t)n * k1 + k] = __float2half_rn(w1[i]);
    } else if (i < sz1 + sz2) {
        int j = i - sz1;
        int k = j / n2, n = j % n2;
        w2t[(size_t)n * k2 + k] = __float2half_rn(w2[j]);
    }
}

__global__ void init_bias4(float4* __restrict__ dst, const float4* __restrict__ bias,
                           int total4, int fmask4)
{
    int i = blockIdx.x * blockDim.x + threadIdx.x;
    if (i < total4) dst[i] = bias[i & fmask4];
}

// ---------------------------------------------------------------------------
// SpMM scatter (float4 lanes) — R5/R8 proven config, verbatim.
// ---------------------------------------------------------------------------
template<int F, int EPG, int G>
__global__ void __launch_bounds__((F / 4) * G)
spmm_scatter4(const float* __restrict__ src, const float* __restrict__ ew,
              const int* __restrict__ row, const int* __restrict__ col,
              float* __restrict__ dst, int E)
{
    constexpr int T = F / 4;
    __shared__ int   s_row[G][EPG];
    __shared__ uint2 s_cw[G][EPG];     // {col, edge_w bits}

    const int g = threadIdx.x / T;
    const int f = threadIdx.x % T;
    const long base = ((long)blockIdx.x * G + g) * EPG;

    long rem = (long)E - base;
    const int cnt = rem <= 0 ? 0 : (rem < EPG ? (int)rem : EPG);

    for (int i = f; i < cnt; i += T) {
        long e = base + i;
        s_row[g][i] = row[e];
        s_cw[g][i]  = make_uint2((unsigned)col[e], __float_as_uint(ew[e]));
    }
    __syncthreads();

    const float4* src4 = reinterpret_cast<const float4*>(src) + f;
    float4 acc = make_float4(0.f, 0.f, 0.f, 0.f);
    int    cur = -1;

    int i = 0;
    const int full = cnt & ~3;
    for (; i < full; i += 4) {
        int rr[4]; float w[4]; float4 v[4];
        #pragma unroll
        for (int j = 0; j < 4; j++) {
            rr[j] = s_row[g][i + j];
            uint2 cw = s_cw[g][i + j];
            w[j] = __uint_as_float(cw.y);
            v[j] = __ldg(&src4[(size_t)cw.x * T]);
        }
        #pragma unroll
        for (int j = 0; j < 4; j++) {
            if (rr[j] != cur) {
                if (cur >= 0) red4(&dst[(size_t)cur * F + 4 * f], acc);
                cur = rr[j];
                acc = make_float4(0.f, 0.f, 0.f, 0.f);
            }
            acc.x = fmaf(w[j], v[j].x, acc.x);
            acc.y = fmaf(w[j], v[j].y, acc.y);
            acc.z = fmaf(w[j], v[j].z, acc.z);
            acc.w = fmaf(w[j], v[j].w, acc.w);
        }
    }
    for (; i < cnt; i++) {
        int   r = s_row[g][i];
        uint2 cw = s_cw[g][i];
        float w  = __uint_as_float(cw.y);
        float4 v = __ldg(&src4[(size_t)cw.x * T]);
        if (r != cur) {
            if (cur >= 0) red4(&dst[(size_t)cur * F + 4 * f], acc);
            cur = r;
            acc = make_float4(0.f, 0.f, 0.f, 0.f);
        }
        acc.x = fmaf(w, v.x, acc.x);
        acc.y = fmaf(w, v.y, acc.y);
        acc.z = fmaf(w, v.z, acc.z);
        acc.w = fmaf(w, v.w, acc.w);
    }
    if (cur >= 0) red4(&dst[(size_t)cur * F + 4 * f], acc);
}

// ===========================================================================
extern "C" void kernel_launch(void* const* d_in, const int* in_sizes, int n_in,
                              void* d_out, int out_size)
{
    const float* x   = (const float*)d_in[0];
    const float* w1  = (const float*)d_in[1];
    const float* b1  = (const float*)d_in[2];
    const float* w2  = (const float*)d_in[3];
    const float* b2  = (const float*)d_in[4];
    const float* ew  = (const float*)d_in[5];
    const int*   row = (const int*)d_in[6];
    const int*   col = (const int*)d_in[7];

    const int nhid  = in_sizes[2];            // 256
    const int nout  = in_sizes[4];            // 64
    const int nfeat = in_sizes[1] / nhid;     // 512
    const int n     = in_sizes[0] / nfeat;    // 50000
    const int E     = in_sizes[5];            // 800000

    void *p1, *p2, *p3, *p4, *p5;
    cudaGetSymbolAddress(&p1, g_h1);
    cudaGetSymbolAddress(&p2, g_h2);
    cudaGetSymbolAddress(&p3, g_h3);
    cudaGetSymbolAddress(&p4, g_w1t);
    cudaGetSymbolAddress(&p5, g_w2t);
    float*  h1  = (float*)p1;
    float*  h2  = (float*)p2;
    float*  h3  = (float*)p3;
    __half* w1t = (__half*)p4;
    __half* w2t = (__half*)p5;
    float*  out = (float*)d_out;

    const int tilesM = (n + 127) / 128;                   // 391

    // 0) both W transposes (fp32 -> fp16 RN), single launch
    {
        int sz1 = nfeat * nhid, sz2 = nhid * nout;
        transpose_round2<<<(sz1 + sz2 + 255) / 256, 256>>>(
            w1, w1t, w2, w2t, sz1, nhid, nfeat, sz2, nout, nhid);
    }

    // 1) h1 = x @ W1   (fp16 mma, 64x64 warp tile; A cvt in registers)
    {
        dim3 grid(nhid / 128, tilesM);
        gemm_mma_big<1><<<grid, 128>>>(x, w1t, h1, n, nfeat, nhid);
    }

    // 2) h2 = b1 + scatter(edge_w * h1[col]) into row
    {
        int total4 = n * nhid / 4;
        init_bias4<<<(total4 + 255) / 256, 256>>>(
            (float4*)h2, (const float4*)b1, total4, nhid / 4 - 1);
        spmm_scatter4<256, 256, 4><<<(E + 1023) / 1024, 256>>>(h1, ew, row, col, h2, E);
    }

    // 3) h3 = relu(h2) @ W2   (relu + cvt fused into A-register path)
    {
        dim3 grid(nout / 64, tilesM);
        gemm_mma<64, 2, 2><<<grid, 256>>>(h2, w2t, h3, n, nhid, nout);
    }

    // 4) out = b2 + scatter(edge_w * h3[col])
    {
        int total4 = n * nout / 4;
        init_bias4<<<(total4 + 255) / 256, 256>>>(
            (float4*)out, (const float4*)b2, total4, nout / 4 - 1);
        spmm_scatter4<64, 128, 16><<<(E + 2047) / 2048, 256>>>(h3, ew, row, col, out, E);
    }
}

// round 10
// speedup vs baseline: 1.8781x; 1.1697x over previous
#include <cuda_runtime.h>
#include <cuda_fp16.h>
#include <cstdint>

// Problem constants (fixed by dataset)
#define MAXN   50000
#define NFEAT  512
#define FHID   256
#define FOUT   64

// Scratch (device globals: allocation-free per harness rules)
__device__ __align__(16) __half g_h1 [MAXN * FHID];    // x @ W1          (fp16)
__device__ __align__(16) __half g_h2 [MAXN * FHID];    // spmm(h1) + b1   (fp16)
__device__ __align__(16) float  g_h3 [MAXN * FOUT];    // relu(h2) @ W2   (fp32)
__device__ __align__(16) __half g_w1t[FHID * NFEAT];   // W1^T fp16
__device__ __align__(16) __half g_w2t[FOUT * FHID];    // W2^T fp16
__device__ int g_rowptr[MAXN + 1];

// ===========================================================================
// helpers
// ===========================================================================
__device__ __forceinline__ uint32_t smem_u32(const void* p) {
    uint32_t a;
    asm("{ .reg .u64 t; cvta.to.shared.u64 t, %1; cvt.u32.u64 %0, t; }"
        : "=r"(a) : "l"(p));
    return a;
}
__device__ __forceinline__ void cp16(uint32_t dst, const void* src) {
    asm volatile("cp.async.cg.shared.global [%0], [%1], 16;"
                 :: "r"(dst), "l"(src) : "memory");
}
#define CP_COMMIT() asm volatile("cp.async.commit_group;" ::: "memory")
#define CP_WAIT0()  asm volatile("cp.async.wait_group 0;" ::: "memory")

// mma.sync m16n8k16 fp16 inputs, fp32 accum (base PTX, sm_80+)
__device__ __forceinline__ void mma16(float* d, const uint32_t* a, const uint32_t* b) {
    asm volatile(
        "mma.sync.aligned.m16n8k16.row.col.f32.f16.f16.f32 "
        "{%0,%1,%2,%3}, {%4,%5,%6,%7}, {%8,%9}, {%0,%1,%2,%3};"
        : "+f"(d[0]), "+f"(d[1]), "+f"(d[2]), "+f"(d[3])
        : "r"(a[0]), "r"(a[1]), "r"(a[2]), "r"(a[3]), "r"(b[0]), "r"(b[1]));
}

__device__ __forceinline__ uint32_t f2h2(float x, float y) {
    __half2 h = __floats2half2_rn(x, y);
    return *reinterpret_cast<uint32_t*>(&h);
}

// ===========================================================================
// GEMM1: 4 warps, warp tile 64x64, BM=128, BN=128, BK=16.
// A fp32 (cvt fp16 in registers), Bt fp16, C fp16.
// ===========================================================================
__global__ void __launch_bounds__(128)
gemm1_mma(const float* __restrict__ A, const __half* __restrict__ Bt,
          __half* __restrict__ C, int M, int K, int Ntot)
{
    constexpr int BM = 128, BN = 128, BK = 16, LDSH = 24;
    __shared__ __half As[2][BM * LDSH];
    __shared__ __half Bs[2][BN * LDSH];

    const int tid  = threadIdx.x;
    const int lane = tid & 31, wid = tid >> 5;
    const int g    = lane >> 2, tig = lane & 3;
    const int wm0  = (wid >> 1) * 64;
    const int wn0  = (wid & 1) * 64;
    const int blockM = blockIdx.y * BM;
    const int blockN = blockIdx.x * BN;

    const int arow = tid >> 2;                   // 0..31
    const int aq   = tid & 3;

    float acc[4][8][4];
    #pragma unroll
    for (int mt = 0; mt < 4; mt++)
        #pragma unroll
        for (int nt = 0; nt < 8; nt++)
            #pragma unroll
            for (int i = 0; i < 4; i++) acc[mt][nt][i] = 0.f;

    auto ldgA = [&](int c, float4* av) {
        const int k0 = c * BK;
        #pragma unroll
        for (int i = 0; i < 4; i++) {
            int r = blockM + arow + i * 32;
            if (r < M)
                av[i] = *reinterpret_cast<const float4*>(&A[(size_t)r * K + k0 + aq * 4]);
            else
                av[i] = make_float4(0.f, 0.f, 0.f, 0.f);
        }
    };
    auto stsA = [&](int buf, float4* av) {
        #pragma unroll
        for (int i = 0; i < 4; i++) {
            float4 v = av[i];
            uint2 h = make_uint2(f2h2(v.x, v.y), f2h2(v.z, v.w));
            *reinterpret_cast<uint2*>(&As[buf][(arow + i * 32) * LDSH + aq * 4]) = h;
        }
    };
    auto cpB = [&](int c, int buf) {
        const int k0 = c * BK;
        #pragma unroll
        for (int i = 0; i < 2; i++) {
            int u = tid + i * 128;
            int r = u >> 1, q = u & 1;
            cp16(smem_u32(&Bs[buf][r * LDSH + q * 8]),
                 &Bt[(size_t)(blockN + r) * K + k0 + q * 8]);
        }
        CP_COMMIT();
    };
    auto compute = [&](int buf) {
        uint32_t a[4][4], b[8][2];
        #pragma unroll
        for (int mt = 0; mt < 4; mt++) {
            const __half* p = &As[buf][(wm0 + mt * 16 + g) * LDSH + 2 * tig];
            a[mt][0] = *reinterpret_cast<const uint32_t*>(p);
            a[mt][1] = *reinterpret_cast<const uint32_t*>(p + 8 * LDSH);
            a[mt][2] = *reinterpret_cast<const uint32_t*>(p + 8);
            a[mt][3] = *reinterpret_cast<const uint32_t*>(p + 8 * LDSH + 8);
        }
        #pragma unroll
        for (int nt = 0; nt < 8; nt++) {
            const __half* pb = &Bs[buf][(wn0 + nt * 8 + g) * LDSH + 2 * tig];
            b[nt][0] = *reinterpret_cast<const uint32_t*>(pb);
            b[nt][1] = *reinterpret_cast<const uint32_t*>(pb + 8);
        }
        #pragma unroll
        for (int mt = 0; mt < 4; mt++)
            #pragma unroll
            for (int nt = 0; nt < 8; nt++)
                mma16(acc[mt][nt], a[mt], b[nt]);
    };

    {
        float4 av[4];
        ldgA(0, av);
        cpB(0, 0);
        stsA(0, av);
        CP_WAIT0();
        __syncthreads();
    }

    const int NC = K / BK;
    for (int c = 0; c < NC; c++) {
        float4 av[4];
        const bool more = (c + 1 < NC);
        if (more) {
            ldgA(c + 1, av);
            cpB(c + 1, (c + 1) & 1);
        }
        compute(c & 1);
        if (more) {
            stsA((c + 1) & 1, av);
            CP_WAIT0();
            __syncthreads();
        }
    }

    // epilogue: fp16 output
    #pragma unroll
    for (int mt = 0; mt < 4; mt++) {
        int r0 = blockM + wm0 + mt * 16 + g;
        int r1 = r0 + 8;
        #pragma unroll
        for (int nt = 0; nt < 8; nt++) {
            int cb = blockN + wn0 + nt * 8 + 2 * tig;
            if (r0 < M)
                *reinterpret_cast<uint32_t*>(&C[(size_t)r0 * Ntot + cb]) =
                    f2h2(acc[mt][nt][0], acc[mt][nt][1]);
            if (r1 < M)
                *reinterpret_cast<uint32_t*>(&C[(size_t)r1 * Ntot + cb]) =
                    f2h2(acc[mt][nt][2], acc[mt][nt][3]);
        }
    }
}

// ===========================================================================
// GEMM2: 8 warps (2Mx4N), BM=128, BN=64, BK=16.
// A fp16 (h2) with relu applied in register staging; Bt fp16; C fp32.
// ===========================================================================
__global__ void __launch_bounds__(256)
gemm2_mma(const __half* __restrict__ A, const __half* __restrict__ Bt,
          float* __restrict__ C, int M, int K, int Ntot)
{
    constexpr int BM = 128, BN = 64, BK = 16, LDSH = 24, WNT = 2;
    __shared__ __half As[2][BM * LDSH];
    __shared__ __half Bs[2][BN * LDSH];

    const int tid  = threadIdx.x;
    const int lane = tid & 31, wid = tid >> 5;
    const int g    = lane >> 2, tig = lane & 3;
    const int wm0  = (wid >> 2) * 64;
    const int wn0  = (wid & 3) * (BN / 4);
    const int blockM = blockIdx.y * BM;
    const int blockN = blockIdx.x * BN;

    const int arow = tid >> 1;                   // 0..127
    const int aq   = tid & 1;                    // which 8-half chunk

    float acc[4][WNT][4];
    #pragma unroll
    for (int mt = 0; mt < 4; mt++)
        #pragma unroll
        for (int nt = 0; nt < WNT; nt++)
            #pragma unroll
            for (int i = 0; i < 4; i++) acc[mt][nt][i] = 0.f;

    const __half2 hzero = __floats2half2_rn(0.f, 0.f);

    auto ldgA = [&](int c, uint4* av) {
        const int k0 = c * BK;
        int r = blockM + arow;
        if (r < M)
            *av = *reinterpret_cast<const uint4*>(&A[(size_t)r * K + k0 + aq * 8]);
        else
            *av = make_uint4(0u, 0u, 0u, 0u);
    };
    auto stsA = [&](int buf, uint4 v) {
        __half2* h = reinterpret_cast<__half2*>(&v);
        #pragma unroll
        for (int i = 0; i < 4; i++) h[i] = __hmax2(h[i], hzero);   // relu
        *reinterpret_cast<uint4*>(&As[buf][arow * LDSH + aq * 8]) = v;
    };
    auto cpB = [&](int c, int buf) {
        const int k0 = c * BK;
        if (tid < BN * 2) {
            int r = tid >> 1, q = tid & 1;
            cp16(smem_u32(&Bs[buf][r * LDSH + q * 8]),
                 &Bt[(size_t)(blockN + r) * K + k0 + q * 8]);
        }
        CP_COMMIT();
    };
    auto compute = [&](int buf) {
        uint32_t a[4][4], b[WNT][2];
        #pragma unroll
        for (int mt = 0; mt < 4; mt++) {
            const __half* p = &As[buf][(wm0 + mt * 16 + g) * LDSH + 2 * tig];
            a[mt][0] = *reinterpret_cast<const uint32_t*>(p);
            a[mt][1] = *reinterpret_cast<const uint32_t*>(p + 8 * LDSH);
            a[mt][2] = *reinterpret_cast<const uint32_t*>(p + 8);
            a[mt][3] = *reinterpret_cast<const uint32_t*>(p + 8 * LDSH + 8);
        }
        #pragma unroll
        for (int nt = 0; nt < WNT; nt++) {
            const __half* pb = &Bs[buf][(wn0 + nt * 8 + g) * LDSH + 2 * tig];
            b[nt][0] = *reinterpret_cast<const uint32_t*>(pb);
            b[nt][1] = *reinterpret_cast<const uint32_t*>(pb + 8);
        }
        #pragma unroll
        for (int mt = 0; mt < 4; mt++)
            #pragma unroll
            for (int nt = 0; nt < WNT; nt++)
                mma16(acc[mt][nt], a[mt], b[nt]);
    };

    {
        uint4 av;
        ldgA(0, &av);
        cpB(0, 0);
        stsA(0, av);
        CP_WAIT0();
        __syncthreads();
    }

    const int NC = K / BK;
    for (int c = 0; c < NC; c++) {
        uint4 av;
        const bool more = (c + 1 < NC);
        if (more) {
            ldgA(c + 1, &av);
            cpB(c + 1, (c + 1) & 1);
        }
        compute(c & 1);
        if (more) {
            stsA((c + 1) & 1, av);
            CP_WAIT0();
            __syncthreads();
        }
    }

    #pragma unroll
    for (int mt = 0; mt < 4; mt++) {
        int r0 = blockM + wm0 + mt * 16 + g;
        int r1 = r0 + 8;
        #pragma unroll
        for (int nt = 0; nt < WNT; nt++) {
            int cb = blockN + wn0 + nt * 8 + 2 * tig;
            if (r0 < M)
                *reinterpret_cast<float2*>(&C[(size_t)r0 * Ntot + cb]) =
                    make_float2(acc[mt][nt][0], acc[mt][nt][1]);
            if (r1 < M)
                *reinterpret_cast<float2*>(&C[(size_t)r1 * Ntot + cb]) =
                    make_float2(acc[mt][nt][2], acc[mt][nt][3]);
        }
    }
}

// ===========================================================================
// Elementwise / indexing kernels
// ===========================================================================
__global__ void transpose_round2(const float* __restrict__ w1, __half* __restrict__ w1t,
                                 const float* __restrict__ w2, __half* __restrict__ w2t,
                                 int sz1, int n1, int k1, int sz2, int n2, int k2)
{
    int i = blockIdx.x * blockDim.x + threadIdx.x;
    if (i < sz1) {
        int k = i / n1, n = i % n1;
        w1t[(size_t)n * k1 + k] = __float2half_rn(w1[i]);
    } else if (i < sz1 + sz2) {
        int j = i - sz1;
        int k = j / n2, n = j % n2;
        w2t[(size_t)n * k2 + k] = __float2half_rn(w2[j]);
    }
}

// row_ptr from sorted row array: rp[r] = first edge with row >= r; rp[N] = E.
__global__ void build_rowptr(const int* __restrict__ row, int* __restrict__ rp,
                             int E, int N)
{
    int e = blockIdx.x * blockDim.x + threadIdx.x;
    if (e >= E) return;
    int r0 = row[e];
    int r1 = (e + 1 < E) ? row[e + 1] : N;
    for (int r = r0 + 1; r <= r1; r++) rp[r] = e + 1;
    if (e == 0)
        for (int r = 0; r <= r0; r++) rp[r] = 0;
}

// ---------------------------------------------------------------------------
// CSR SpMM, fp16 src -> fp16 dst (layer 1):
//   dst[r] = bias + sum_{e in [rp[r],rp[r+1])} ew[e] * src[col[e]]
// One group of T=F/4 threads per row; register fp32 accum; direct store.
// ---------------------------------------------------------------------------
template<int F>   // F = 256
__global__ void __launch_bounds__(256)
spmm_csr_h2h(const __half* __restrict__ src, const float* __restrict__ bias,
             const float* __restrict__ ew, const int* __restrict__ rp,
             const int* __restrict__ col, __half* __restrict__ dst, int N)
{
    constexpr int T = F / 4;                 // 64 threads, 4 halves each
    constexpr int G = 256 / T;               // 4 rows per block
    const int g = threadIdx.x / T;
    const int f = threadIdx.x % T;
    const int r = blockIdx.x * G + g;
    if (r >= N) return;

    const int s = __ldg(&rp[r]);
    const int e_end = __ldg(&rp[r + 1]);

    float a0 = 0.f, a1 = 0.f, a2 = 0.f, a3 = 0.f;
    const uint2* src2 = reinterpret_cast<const uint2*>(src) + f;   // row stride T

    int i = s;
    for (; i + 4 <= e_end; i += 4) {
        float w[4]; uint2 v[4];
        #pragma unroll
        for (int j = 0; j < 4; j++) {                 // 4 gathers in flight
            int c = __ldg(&col[i + j]);
            w[j]  = __ldg(&ew[i + j]);
            v[j]  = __ldg(&src2[(size_t)c * T]);
        }
        #pragma unroll
        for (int j = 0; j < 4; j++) {
            float2 f0 = __half22float2(*reinterpret_cast<__half2*>(&v[j].x));
            float2 f1 = __half22float2(*reinterpret_cast<__half2*>(&v[j].y));
            a0 = fmaf(w[j], f0.x, a0); a1 = fmaf(w[j], f0.y, a1);
            a2 = fmaf(w[j], f1.x, a2); a3 = fmaf(w[j], f1.y, a3);
        }
    }
    for (; i < e_end; i++) {
        int c = __ldg(&col[i]);
        float w = __ldg(&ew[i]);
        uint2 v = __ldg(&src2[(size_t)c * T]);
        float2 f0 = __half22float2(*reinterpret_cast<__half2*>(&v.x));
        float2 f1 = __half22float2(*reinterpret_cast<__half2*>(&v.y));
        a0 = fmaf(w, f0.x, a0); a1 = fmaf(w, f0.y, a1);
        a2 = fmaf(w, f1.x, a2); a3 = fmaf(w, f1.y, a3);
    }

    float4 b = __ldg(reinterpret_cast<const float4*>(bias) + f);
    uint2 o = make_uint2(f2h2(a0 + b.x, a1 + b.y), f2h2(a2 + b.z, a3 + b.w));
    *(reinterpret_cast<uint2*>(dst) + (size_t)r * T + f) = o;
}

// ---------------------------------------------------------------------------
// CSR SpMM, fp32 src -> fp32 dst (layer 2): dst = bias + A @ src
// ---------------------------------------------------------------------------
template<int F>   // F = 64
__global__ void __launch_bounds__(256)
spmm_csr_f2f(const float* __restrict__ src, const float* __restrict__ bias,
             const float* __restrict__ ew, const int* __restrict__ rp,
             const int* __restrict__ col, float* __restrict__ dst, int N)
{
    constexpr int T = F / 4;                 // 16 threads, float4 each
    constexpr int G = 256 / T;               // 16 rows per block
    const int g = threadIdx.x / T;
    const int f = threadIdx.x % T;
    const int r = blockIdx.x * G + g;
    if (r >= N) return;

    const int s = __ldg(&rp[r]);
    const int e_end = __ldg(&rp[r + 1]);

    float4 acc = make_float4(0.f, 0.f, 0.f, 0.f);
    const float4* src4 = reinterpret_cast<const float4*>(src) + f;

    int i = s;
    for (; i + 4 <= e_end; i += 4) {
        float w[4]; float4 v[4];
        #pragma unroll
        for (int j = 0; j < 4; j++) {
            int c = __ldg(&col[i + j]);
            w[j]  = __ldg(&ew[i + j]);
            v[j]  = __ldg(&src4[(size_t)c * T]);
        }
        #pragma unroll
        for (int j = 0; j < 4; j++) {
            acc.x = fmaf(w[j], v[j].x, acc.x);
            acc.y = fmaf(w[j], v[j].y, acc.y);
            acc.z = fmaf(w[j], v[j].z, acc.z);
            acc.w = fmaf(w[j], v[j].w, acc.w);
        }
    }
    for (; i < e_end; i++) {
        int c = __ldg(&col[i]);
        float w = __ldg(&ew[i]);
        float4 v = __ldg(&src4[(size_t)c * T]);
        acc.x = fmaf(w, v.x, acc.x);
        acc.y = fmaf(w, v.y, acc.y);
        acc.z = fmaf(w, v.z, acc.z);
        acc.w = fmaf(w, v.w, acc.w);
    }

    float4 b = __ldg(reinterpret_cast<const float4*>(bias) + f);
    acc.x += b.x; acc.y += b.y; acc.z += b.z; acc.w += b.w;
    *(reinterpret_cast<float4*>(dst) + (size_t)r * T + f) = acc;
}

// ===========================================================================
extern "C" void kernel_launch(void* const* d_in, const int* in_sizes, int n_in,
                              void* d_out, int out_size)
{
    const float* x   = (const float*)d_in[0];
    const float* w1  = (const float*)d_in[1];
    const float* b1  = (const float*)d_in[2];
    const float* w2  = (const float*)d_in[3];
    const float* b2  = (const float*)d_in[4];
    const float* ew  = (const float*)d_in[5];
    const int*   row = (const int*)d_in[6];
    const int*   col = (const int*)d_in[7];

    const int nhid  = in_sizes[2];            // 256
    const int nout  = in_sizes[4];            // 64
    const int nfeat = in_sizes[1] / nhid;     // 512
    const int n     = in_sizes[0] / nfeat;    // 50000
    const int E     = in_sizes[5];            // 800000

    void *p1, *p2, *p3, *p4, *p5, *p6;
    cudaGetSymbolAddress(&p1, g_h1);
    cudaGetSymbolAddress(&p2, g_h2);
    cudaGetSymbolAddress(&p3, g_h3);
    cudaGetSymbolAddress(&p4, g_w1t);
    cudaGetSymbolAddress(&p5, g_w2t);
    cudaGetSymbolAddress(&p6, g_rowptr);
    __half* h1  = (__half*)p1;
    __half* h2  = (__half*)p2;
    float*  h3  = (float*)p3;
    __half* w1t = (__half*)p4;
    __half* w2t = (__half*)p5;
    int*    rp  = (int*)p6;
    float*  out = (float*)d_out;

    const int tilesM = (n + 127) / 128;                   // 391

    // 0) weight transposes (fp32 -> fp16) + row_ptr from sorted rows
    {
        int sz1 = nfeat * nhid, sz2 = nhid * nout;
        transpose_round2<<<(sz1 + sz2 + 255) / 256, 256>>>(
            w1, w1t, w2, w2t, sz1, nhid, nfeat, sz2, nout, nhid);
        build_rowptr<<<(E + 255) / 256, 256>>>(row, rp, E, n);
    }

    // 1) h1 = x @ W1   (fp16 out)
    {
        dim3 grid(nhid / 128, tilesM);
        gemm1_mma<<<grid, 128>>>(x, w1t, h1, n, nfeat, nhid);
    }

    // 2) h2 = b1 + A @ h1   (CSR, fp16 in/out, no atomics, no init)
    spmm_csr_h2h<256><<<(n + 3) / 4, 256>>>(h1, b1, ew, rp, col, h2, n);

    // 3) h3 = relu(h2) @ W2   (A fp16 + relu in staging; fp32 out)
    {
        dim3 grid(nout / 64, tilesM);
        gemm2_mma<<<grid, 256>>>(h2, w2t, h3, n, nhid, nout);
    }

    // 4) out = b2 + A @ h3   (CSR, fp32, direct store)
    spmm_csr_f2f<64><<<(n + 15) / 16, 256>>>(h3, b2, ew, rp, col, out, n);
}

// round 11
// speedup vs baseline: 2.1889x; 1.1655x over previous
#include <cuda_runtime.h>
#include <cuda_fp16.h>
#include <cstdint>

// Problem constants (fixed by dataset)
#define MAXN   50000
#define NFEAT  512
#define FHID   256
#define FOUT   64

// Scratch (device globals: allocation-free per harness rules)
__device__ __align__(16) __half g_h1 [MAXN * FHID];    // x @ W1          (fp16)
__device__ __align__(16) __half g_h2 [MAXN * FHID];    // spmm(h1) + b1   (fp16)
__device__ __align__(16) __half g_h3 [MAXN * FOUT];    // relu(h2) @ W2   (fp16)
__device__ __align__(16) __half g_w1t[FHID * NFEAT];   // W1^T fp16
__device__ __align__(16) __half g_w2t[FOUT * FHID];    // W2^T fp16
__device__ int g_rowptr[MAXN + 1];

// ===========================================================================
// helpers
// ===========================================================================
__device__ __forceinline__ uint32_t smem_u32(const void* p) {
    uint32_t a;
    asm("{ .reg .u64 t; cvta.to.shared.u64 t, %1; cvt.u32.u64 %0, t; }"
        : "=r"(a) : "l"(p));
    return a;
}
__device__ __forceinline__ void cp16(uint32_t dst, const void* src) {
    asm volatile("cp.async.cg.shared.global [%0], [%1], 16;"
                 :: "r"(dst), "l"(src) : "memory");
}
#define CP_COMMIT() asm volatile("cp.async.commit_group;" ::: "memory")
#define CP_WAIT0()  asm volatile("cp.async.wait_group 0;" ::: "memory")

// mma.sync m16n8k16 fp16 inputs, fp32 accum (base PTX, sm_80+)
__device__ __forceinline__ void mma16(float* d, const uint32_t* a, const uint32_t* b) {
    asm volatile(
        "mma.sync.aligned.m16n8k16.row.col.f32.f16.f16.f32 "
        "{%0,%1,%2,%3}, {%4,%5,%6,%7}, {%8,%9}, {%0,%1,%2,%3};"
        : "+f"(d[0]), "+f"(d[1]), "+f"(d[2]), "+f"(d[3])
        : "r"(a[0]), "r"(a[1]), "r"(a[2]), "r"(a[3]), "r"(b[0]), "r"(b[1]));
}

__device__ __forceinline__ uint32_t f2h2(float x, float y) {
    __half2 h = __floats2half2_rn(x, y);
    return *reinterpret_cast<uint32_t*>(&h);
}

// ===========================================================================
// GEMM1: 4 warps, warp tile 64x64, BM=128, BN=128, BK=32 (16 sync stages).
// A fp32 (cvt fp16 in registers), Bt fp16, C fp16.  LDSH=40 (conflict-free).
// ===========================================================================
__global__ void __launch_bounds__(128)
gemm1_mma(const float* __restrict__ A, const __half* __restrict__ Bt,
          __half* __restrict__ C, int M, int K, int Ntot)
{
    constexpr int BM = 128, BN = 128, BK = 32, LDSH = 40;
    __shared__ __half As[2][BM * LDSH];
    __shared__ __half Bs[2][BN * LDSH];

    const int tid  = threadIdx.x;
    const int lane = tid & 31, wid = tid >> 5;
    const int g    = lane >> 2, tig = lane & 3;
    const int wm0  = (wid >> 1) * 64;
    const int wn0  = (wid & 1) * 64;
    const int blockM = blockIdx.y * BM;
    const int blockN = blockIdx.x * BN;

    const int arow = tid >> 3;                   // 0..15 (A rows: arow + 16i)
    const int aq   = tid & 7;                    // float4 slot within 32-col row

    float acc[4][8][4];
    #pragma unroll
    for (int mt = 0; mt < 4; mt++)
        #pragma unroll
        for (int nt = 0; nt < 8; nt++)
            #pragma unroll
            for (int i = 0; i < 4; i++) acc[mt][nt][i] = 0.f;

    auto ldgA = [&](int c, float4* av) {
        const int k0 = c * BK;
        #pragma unroll
        for (int i = 0; i < 8; i++) {
            int r = blockM + arow + i * 16;
            if (r < M)
                av[i] = *reinterpret_cast<const float4*>(&A[(size_t)r * K + k0 + aq * 4]);
            else
                av[i] = make_float4(0.f, 0.f, 0.f, 0.f);
        }
    };
    auto stsA = [&](int buf, float4* av) {
        #pragma unroll
        for (int i = 0; i < 8; i++) {
            float4 v = av[i];
            uint2 h = make_uint2(f2h2(v.x, v.y), f2h2(v.z, v.w));
            *reinterpret_cast<uint2*>(&As[buf][(arow + i * 16) * LDSH + aq * 4]) = h;
        }
    };
    auto cpB = [&](int c, int buf) {
        const int k0 = c * BK;
        #pragma unroll
        for (int i = 0; i < 4; i++) {            // BN rows x 4 x 16B chunks
            int u = tid + i * 128;
            int r = u >> 2, q = u & 3;
            cp16(smem_u32(&Bs[buf][r * LDSH + q * 8]),
                 &Bt[(size_t)(blockN + r) * K + k0 + q * 8]);
        }
        CP_COMMIT();
    };
    auto compute = [&](int buf) {
        #pragma unroll
        for (int ks = 0; ks < 2; ks++) {
            uint32_t a[4][4], b[8][2];
            #pragma unroll
            for (int mt = 0; mt < 4; mt++) {
                const __half* p = &As[buf][(wm0 + mt * 16 + g) * LDSH + ks * 16 + 2 * tig];
                a[mt][0] = *reinterpret_cast<const uint32_t*>(p);
                a[mt][1] = *reinterpret_cast<const uint32_t*>(p + 8 * LDSH);
                a[mt][2] = *reinterpret_cast<const uint32_t*>(p + 8);
                a[mt][3] = *reinterpret_cast<const uint32_t*>(p + 8 * LDSH + 8);
            }
            #pragma unroll
            for (int nt = 0; nt < 8; nt++) {
                const __half* pb = &Bs[buf][(wn0 + nt * 8 + g) * LDSH + ks * 16 + 2 * tig];
                b[nt][0] = *reinterpret_cast<const uint32_t*>(pb);
                b[nt][1] = *reinterpret_cast<const uint32_t*>(pb + 8);
            }
            #pragma unroll
            for (int mt = 0; mt < 4; mt++)
                #pragma unroll
                for (int nt = 0; nt < 8; nt++)
                    mma16(acc[mt][nt], a[mt], b[nt]);
        }
    };

    {
        float4 av[8];
        ldgA(0, av);
        cpB(0, 0);
        stsA(0, av);
        CP_WAIT0();
        __syncthreads();
    }

    const int NC = K / BK;                       // 16
    for (int c = 0; c < NC; c++) {
        float4 av[8];
        const bool more = (c + 1 < NC);
        if (more) {
            ldgA(c + 1, av);
            cpB(c + 1, (c + 1) & 1);
        }
        compute(c & 1);
        if (more) {
            stsA((c + 1) & 1, av);
            CP_WAIT0();
            __syncthreads();
        }
    }

    // epilogue: fp16 output
    #pragma unroll
    for (int mt = 0; mt < 4; mt++) {
        int r0 = blockM + wm0 + mt * 16 + g;
        int r1 = r0 + 8;
        #pragma unroll
        for (int nt = 0; nt < 8; nt++) {
            int cb = blockN + wn0 + nt * 8 + 2 * tig;
            if (r0 < M)
                *reinterpret_cast<uint32_t*>(&C[(size_t)r0 * Ntot + cb]) =
                    f2h2(acc[mt][nt][0], acc[mt][nt][1]);
            if (r1 < M)
                *reinterpret_cast<uint32_t*>(&C[(size_t)r1 * Ntot + cb]) =
                    f2h2(acc[mt][nt][2], acc[mt][nt][3]);
        }
    }
}

// ===========================================================================
// GEMM2: 8 warps (2Mx4N), BM=128, BN=64, BK=16.
// A fp16 (h2) with relu in register staging; Bt fp16; C fp16.
// ===========================================================================
__global__ void __launch_bounds__(256)
gemm2_mma(const __half* __restrict__ A, const __half* __restrict__ Bt,
          __half* __restrict__ C, int M, int K, int Ntot)
{
    constexpr int BM = 128, BN = 64, BK = 16, LDSH = 24, WNT = 2;
    __shared__ __half As[2][BM * LDSH];
    __shared__ __half Bs[2][BN * LDSH];

    const int tid  = threadIdx.x;
    const int lane = tid & 31, wid = tid >> 5;
    const int g    = lane >> 2, tig = lane & 3;
    const int wm0  = (wid >> 2) * 64;
    const int wn0  = (wid & 3) * (BN / 4);
    const int blockM = blockIdx.y * BM;
    const int blockN = blockIdx.x * BN;

    const int arow = tid >> 1;                   // 0..127
    const int aq   = tid & 1;

    float acc[4][WNT][4];
    #pragma unroll
    for (int mt = 0; mt < 4; mt++)
        #pragma unroll
        for (int nt = 0; nt < WNT; nt++)
            #pragma unroll
            for (int i = 0; i < 4; i++) acc[mt][nt][i] = 0.f;

    const __half2 hzero = __floats2half2_rn(0.f, 0.f);

    auto ldgA = [&](int c, uint4* av) {
        const int k0 = c * BK;
        int r = blockM + arow;
        if (r < M)
            *av = *reinterpret_cast<const uint4*>(&A[(size_t)r * K + k0 + aq * 8]);
        else
            *av = make_uint4(0u, 0u, 0u, 0u);
    };
    auto stsA = [&](int buf, uint4 v) {
        __half2* h = reinterpret_cast<__half2*>(&v);
        #pragma unroll
        for (int i = 0; i < 4; i++) h[i] = __hmax2(h[i], hzero);   // relu
        *reinterpret_cast<uint4*>(&As[buf][arow * LDSH + aq * 8]) = v;
    };
    auto cpB = [&](int c, int buf) {
        const int k0 = c * BK;
        if (tid < BN * 2) {
            int r = tid >> 1, q = tid & 1;
            cp16(smem_u32(&Bs[buf][r * LDSH + q * 8]),
                 &Bt[(size_t)(blockN + r) * K + k0 + q * 8]);
        }
        CP_COMMIT();
    };
    auto compute = [&](int buf) {
        uint32_t a[4][4], b[WNT][2];
        #pragma unroll
        for (int mt = 0; mt < 4; mt++) {
            const __half* p = &As[buf][(wm0 + mt * 16 + g) * LDSH + 2 * tig];
            a[mt][0] = *reinterpret_cast<const uint32_t*>(p);
            a[mt][1] = *reinterpret_cast<const uint32_t*>(p + 8 * LDSH);
            a[mt][2] = *reinterpret_cast<const uint32_t*>(p + 8);
            a[mt][3] = *reinterpret_cast<const uint32_t*>(p + 8 * LDSH + 8);
        }
        #pragma unroll
        for (int nt = 0; nt < WNT; nt++) {
            const __half* pb = &Bs[buf][(wn0 + nt * 8 + g) * LDSH + 2 * tig];
            b[nt][0] = *reinterpret_cast<const uint32_t*>(pb);
            b[nt][1] = *reinterpret_cast<const uint32_t*>(pb + 8);
        }
        #pragma unroll
        for (int mt = 0; mt < 4; mt++)
            #pragma unroll
            for (int nt = 0; nt < WNT; nt++)
                mma16(acc[mt][nt], a[mt], b[nt]);
    };

    {
        uint4 av;
        ldgA(0, &av);
        cpB(0, 0);
        stsA(0, av);
        CP_WAIT0();
        __syncthreads();
    }

    const int NC = K / BK;
    for (int c = 0; c < NC; c++) {
        uint4 av;
        const bool more = (c + 1 < NC);
        if (more) {
            ldgA(c + 1, &av);
            cpB(c + 1, (c + 1) & 1);
        }
        compute(c & 1);
        if (more) {
            stsA((c + 1) & 1, av);
            CP_WAIT0();
            __syncthreads();
        }
    }

    // epilogue: fp16 output
    #pragma unroll
    for (int mt = 0; mt < 4; mt++) {
        int r0 = blockM + wm0 + mt * 16 + g;
        int r1 = r0 + 8;
        #pragma unroll
        for (int nt = 0; nt < WNT; nt++) {
            int cb = blockN + wn0 + nt * 8 + 2 * tig;
            if (r0 < M)
                *reinterpret_cast<uint32_t*>(&C[(size_t)r0 * Ntot + cb]) =
                    f2h2(acc[mt][nt][0], acc[mt][nt][1]);
            if (r1 < M)
                *reinterpret_cast<uint32_t*>(&C[(size_t)r1 * Ntot + cb]) =
                    f2h2(acc[mt][nt][2], acc[mt][nt][3]);
        }
    }
}

// ===========================================================================
// Elementwise / indexing kernels
// ===========================================================================
__global__ void transpose_round2(const float* __restrict__ w1, __half* __restrict__ w1t,
                                 const float* __restrict__ w2, __half* __restrict__ w2t,
                                 int sz1, int n1, int k1, int sz2, int n2, int k2)
{
    int i = blockIdx.x * blockDim.x + threadIdx.x;
    if (i < sz1) {
        int k = i / n1, n = i % n1;
        w1t[(size_t)n * k1 + k] = __float2half_rn(w1[i]);
    } else if (i < sz1 + sz2) {
        int j = i - sz1;
        int k = j / n2, n = j % n2;
        w2t[(size_t)n * k2 + k] = __float2half_rn(w2[j]);
    }
}

// row_ptr from sorted row array
__global__ void build_rowptr(const int* __restrict__ row, int* __restrict__ rp,
                             int E, int N)
{
    int e = blockIdx.x * blockDim.x + threadIdx.x;
    if (e >= E) return;
    int r0 = row[e];
    int r1 = (e + 1 < E) ? row[e + 1] : N;
    for (int r = r0 + 1; r <= r1; r++) rp[r] = e + 1;
    if (e == 0)
        for (int r = 0; r <= r0; r++) rp[r] = 0;
}

// ---------------------------------------------------------------------------
// CSR SpMM, fp16 src -> fp16 dst (layer 1), F=256.
// ---------------------------------------------------------------------------
template<int F>
__global__ void __launch_bounds__(256)
spmm_csr_h2h(const __half* __restrict__ src, const float* __restrict__ bias,
             const float* __restrict__ ew, const int* __restrict__ rp,
             const int* __restrict__ col, __half* __restrict__ dst, int N)
{
    constexpr int T = F / 4;
    constexpr int G = 256 / T;
    const int g = threadIdx.x / T;
    const int f = threadIdx.x % T;
    const int r = blockIdx.x * G + g;
    if (r >= N) return;

    const int s = __ldg(&rp[r]);
    const int e_end = __ldg(&rp[r + 1]);

    float a0 = 0.f, a1 = 0.f, a2 = 0.f, a3 = 0.f;
    const uint2* src2 = reinterpret_cast<const uint2*>(src) + f;

    int i = s;
    for (; i + 4 <= e_end; i += 4) {
        float w[4]; uint2 v[4];
        #pragma unroll
        for (int j = 0; j < 4; j++) {
            int c = __ldg(&col[i + j]);
            w[j]  = __ldg(&ew[i + j]);
            v[j]  = __ldg(&src2[(size_t)c * T]);
        }
        #pragma unroll
        for (int j = 0; j < 4; j++) {
            float2 f0 = __half22float2(*reinterpret_cast<__half2*>(&v[j].x));
            float2 f1 = __half22float2(*reinterpret_cast<__half2*>(&v[j].y));
            a0 = fmaf(w[j], f0.x, a0); a1 = fmaf(w[j], f0.y, a1);
            a2 = fmaf(w[j], f1.x, a2); a3 = fmaf(w[j], f1.y, a3);
        }
    }
    for (; i < e_end; i++) {
        int c = __ldg(&col[i]);
        float w = __ldg(&ew[i]);
        uint2 v = __ldg(&src2[(size_t)c * T]);
        float2 f0 = __half22float2(*reinterpret_cast<__half2*>(&v.x));
        float2 f1 = __half22float2(*reinterpret_cast<__half2*>(&v.y));
        a0 = fmaf(w, f0.x, a0); a1 = fmaf(w, f0.y, a1);
        a2 = fmaf(w, f1.x, a2); a3 = fmaf(w, f1.y, a3);
    }

    float4 b = __ldg(reinterpret_cast<const float4*>(bias) + f);
    uint2 o = make_uint2(f2h2(a0 + b.x, a1 + b.y), f2h2(a2 + b.z, a3 + b.w));
    *(reinterpret_cast<uint2*>(dst) + (size_t)r * T + f) = o;
}

// ---------------------------------------------------------------------------
// CSR SpMM, fp16 src -> fp32 dst (layer 2), F=64.
// ---------------------------------------------------------------------------
template<int F>
__global__ void __launch_bounds__(256)
spmm_csr_h2f(const __half* __restrict__ src, const float* __restrict__ bias,
             const float* __restrict__ ew, const int* __restrict__ rp,
             const int* __restrict__ col, float* __restrict__ dst, int N)
{
    constexpr int T = F / 4;                 // 16 threads, 4 halves each
    constexpr int G = 256 / T;               // 16 rows per block
    const int g = threadIdx.x / T;
    const int f = threadIdx.x % T;
    const int r = blockIdx.x * G + g;
    if (r >= N) return;

    const int s = __ldg(&rp[r]);
    const int e_end = __ldg(&rp[r + 1]);

    float a0 = 0.f, a1 = 0.f, a2 = 0.f, a3 = 0.f;
    const uint2* src2 = reinterpret_cast<const uint2*>(src) + f;

    int i = s;
    for (; i + 4 <= e_end; i += 4) {
        float w[4]; uint2 v[4];
        #pragma unroll
        for (int j = 0; j < 4; j++) {
            int c = __ldg(&col[i + j]);
            w[j]  = __ldg(&ew[i + j]);
            v[j]  = __ldg(&src2[(size_t)c * T]);
        }
        #pragma unroll
        for (int j = 0; j < 4; j++) {
            float2 f0 = __half22float2(*reinterpret_cast<__half2*>(&v[j].x));
            float2 f1 = __half22float2(*reinterpret_cast<__half2*>(&v[j].y));
            a0 = fmaf(w[j], f0.x, a0); a1 = fmaf(w[j], f0.y, a1);
            a2 = fmaf(w[j], f1.x, a2); a3 = fmaf(w[j], f1.y, a3);
        }
    }
    for (; i < e_end; i++) {
        int c = __ldg(&col[i]);
        float w = __ldg(&ew[i]);
        uint2 v = __ldg(&src2[(size_t)c * T]);
        float2 f0 = __half22float2(*reinterpret_cast<__half2*>(&v.x));
        float2 f1 = __half22float2(*reinterpret_cast<__half2*>(&v.y));
        a0 = fmaf(w, f0.x, a0); a1 = fmaf(w, f0.y, a1);
        a2 = fmaf(w, f1.x, a2); a3 = fmaf(w, f1.y, a3);
    }

    float4 b = __ldg(reinterpret_cast<const float4*>(bias) + f);
    *(reinterpret_cast<float4*>(dst) + (size_t)r * T + f) =
        make_float4(a0 + b.x, a1 + b.y, a2 + b.z, a3 + b.w);
}

// ===========================================================================
extern "C" void kernel_launch(void* const* d_in, const int* in_sizes, int n_in,
                              void* d_out, int out_size)
{
    const float* x   = (const float*)d_in[0];
    const float* w1  = (const float*)d_in[1];
    const float* b1  = (const float*)d_in[2];
    const float* w2  = (const float*)d_in[3];
    const float* b2  = (const float*)d_in[4];
    const float* ew  = (const float*)d_in[5];
    const int*   row = (const int*)d_in[6];
    const int*   col = (const int*)d_in[7];

    const int nhid  = in_sizes[2];            // 256
    const int nout  = in_sizes[4];            // 64
    const int nfeat = in_sizes[1] / nhid;     // 512
    const int n     = in_sizes[0] / nfeat;    // 50000
    const int E     = in_sizes[5];            // 800000

    void *p1, *p2, *p3, *p4, *p5, *p6;
    cudaGetSymbolAddress(&p1, g_h1);
    cudaGetSymbolAddress(&p2, g_h2);
    cudaGetSymbolAddress(&p3, g_h3);
    cudaGetSymbolAddress(&p4, g_w1t);
    cudaGetSymbolAddress(&p5, g_w2t);
    cudaGetSymbolAddress(&p6, g_rowptr);
    __half* h1  = (__half*)p1;
    __half* h2  = (__half*)p2;
    __half* h3  = (__half*)p3;
    __half* w1t = (__half*)p4;
    __half* w2t = (__half*)p5;
    int*    rp  = (int*)p6;
    float*  out = (float*)d_out;

    const int tilesM = (n + 127) / 128;                   // 391

    // 0) weight transposes (fp32 -> fp16) + row_ptr from sorted rows
    {
        int sz1 = nfeat * nhid, sz2 = nhid * nout;
        transpose_round2<<<(sz1 + sz2 + 255) / 256, 256>>>(
            w1, w1t, w2, w2t, sz1, nhid, nfeat, sz2, nout, nhid);
        build_rowptr<<<(E + 255) / 256, 256>>>(row, rp, E, n);
    }

    // 1) h1 = x @ W1   (BK=32, fp16 out)
    {
        dim3 grid(nhid / 128, tilesM);
        gemm1_mma<<<grid, 128>>>(x, w1t, h1, n, nfeat, nhid);
    }

    // 2) h2 = b1 + A @ h1   (CSR, fp16 in/out)
    spmm_csr_h2h<256><<<(n + 3) / 4, 256>>>(h1, b1, ew, rp, col, h2, n);

    // 3) h3 = relu(h2) @ W2   (fp16 in/out)
    {
        dim3 grid(nout / 64, tilesM);
        gemm2_mma<<<grid, 256>>>(h2, w2t, h3, n, nhid, nout);
    }

    // 4) out = b2 + A @ h3   (CSR, fp16 gather, fp32 out)
    spmm_csr_h2f<64><<<(n + 15) / 16, 256>>>(h3, b2, ew, rp, col, out, n);
}

// round 12
// speedup vs baseline: 2.3072x; 1.0541x over previous
#include <cuda_runtime.h>
#include <cuda_fp16.h>
#include <cstdint>

// Problem constants (fixed by dataset)
#define MAXN   50000
#define NFEAT  512
#define FHID   256
#define FOUT   64

// Scratch (device globals: allocation-free per harness rules)
__device__ __align__(16) __half g_h1 [MAXN * FHID];    // x @ W1          (fp16)
__device__ __align__(16) __half g_h2 [MAXN * FHID];    // spmm(h1) + b1   (fp16)
__device__ __align__(16) __half g_h3 [MAXN * FOUT];    // relu(h2) @ W2   (fp16)
__device__ __align__(16) __half g_w1t[FHID * NFEAT];   // W1^T fp16
__device__ __align__(16) __half g_w2t[FOUT * FHID];    // W2^T fp16
__device__ int g_rowptr[MAXN + 1];

// ===========================================================================
// helpers
// ===========================================================================
__device__ __forceinline__ uint32_t smem_u32(const void* p) {
    uint32_t a;
    asm("{ .reg .u64 t; cvta.to.shared.u64 t, %1; cvt.u32.u64 %0, t; }"
        : "=r"(a) : "l"(p));
    return a;
}
__device__ __forceinline__ void cp16(uint32_t dst, const void* src) {
    asm volatile("cp.async.cg.shared.global [%0], [%1], 16;"
                 :: "r"(dst), "l"(src) : "memory");
}
#define CP_COMMIT() asm volatile("cp.async.commit_group;" ::: "memory")
#define CP_WAIT0()  asm volatile("cp.async.wait_group 0;" ::: "memory")

// mma.sync m16n8k16 fp16 inputs, fp32 accum (base PTX, sm_80+)
__device__ __forceinline__ void mma16(float* d, const uint32_t* a, const uint32_t* b) {
    asm volatile(
        "mma.sync.aligned.m16n8k16.row.col.f32.f16.f16.f32 "
        "{%0,%1,%2,%3}, {%4,%5,%6,%7}, {%8,%9}, {%0,%1,%2,%3};"
        : "+f"(d[0]), "+f"(d[1]), "+f"(d[2]), "+f"(d[3])
        : "r"(a[0]), "r"(a[1]), "r"(a[2]), "r"(a[3]), "r"(b[0]), "r"(b[1]));
}

__device__ __forceinline__ uint32_t f2h2(float x, float y) {
    __half2 h = __floats2half2_rn(x, y);
    return *reinterpret_cast<uint32_t*>(&h);
}

// accumulate 8 halves (uint4) * w into fp32 acc[8]
__device__ __forceinline__ void acc8(float* a, uint4 v, float w) {
    const uint32_t* u = reinterpret_cast<const uint32_t*>(&v);
    #pragma unroll
    for (int q = 0; q < 4; q++) {
        float2 f = __half22float2(*reinterpret_cast<const __half2*>(&u[q]));
        a[2*q]   = fmaf(w, f.x, a[2*q]);
        a[2*q+1] = fmaf(w, f.y, a[2*q+1]);
    }
}

// ===========================================================================
// GEMM1: 4 warps, warp tile 64x64, BM=128, BN=128, BK=32 (16 sync stages).
// A fp32 (cvt fp16 in registers), Bt fp16, C fp16.  LDSH=40 (conflict-free).
// ===========================================================================
__global__ void __launch_bounds__(128)
gemm1_mma(const float* __restrict__ A, const __half* __restrict__ Bt,
          __half* __restrict__ C, int M, int K, int Ntot)
{
    constexpr int BM = 128, BN = 128, BK = 32, LDSH = 40;
    __shared__ __half As[2][BM * LDSH];
    __shared__ __half Bs[2][BN * LDSH];

    const int tid  = threadIdx.x;
    const int lane = tid & 31, wid = tid >> 5;
    const int g    = lane >> 2, tig = lane & 3;
    const int wm0  = (wid >> 1) * 64;
    const int wn0  = (wid & 1) * 64;
    const int blockM = blockIdx.y * BM;
    const int blockN = blockIdx.x * BN;

    const int arow = tid >> 3;                   // 0..15 (A rows: arow + 16i)
    const int aq   = tid & 7;

    float acc[4][8][4];
    #pragma unroll
    for (int mt = 0; mt < 4; mt++)
        #pragma unroll
        for (int nt = 0; nt < 8; nt++)
            #pragma unroll
            for (int i = 0; i < 4; i++) acc[mt][nt][i] = 0.f;

    auto ldgA = [&](int c, float4* av) {
        const int k0 = c * BK;
        #pragma unroll
        for (int i = 0; i < 8; i++) {
            int r = blockM + arow + i * 16;
            if (r < M)
                av[i] = *reinterpret_cast<const float4*>(&A[(size_t)r * K + k0 + aq * 4]);
            else
                av[i] = make_float4(0.f, 0.f, 0.f, 0.f);
        }
    };
    auto stsA = [&](int buf, float4* av) {
        #pragma unroll
        for (int i = 0; i < 8; i++) {
            float4 v = av[i];
            uint2 h = make_uint2(f2h2(v.x, v.y), f2h2(v.z, v.w));
            *reinterpret_cast<uint2*>(&As[buf][(arow + i * 16) * LDSH + aq * 4]) = h;
        }
    };
    auto cpB = [&](int c, int buf) {
        const int k0 = c * BK;
        #pragma unroll
        for (int i = 0; i < 4; i++) {
            int u = tid + i * 128;
            int r = u >> 2, q = u & 3;
            cp16(smem_u32(&Bs[buf][r * LDSH + q * 8]),
                 &Bt[(size_t)(blockN + r) * K + k0 + q * 8]);
        }
        CP_COMMIT();
    };
    auto compute = [&](int buf) {
        #pragma unroll
        for (int ks = 0; ks < 2; ks++) {
            uint32_t a[4][4], b[8][2];
            #pragma unroll
            for (int mt = 0; mt < 4; mt++) {
                const __half* p = &As[buf][(wm0 + mt * 16 + g) * LDSH + ks * 16 + 2 * tig];
                a[mt][0] = *reinterpret_cast<const uint32_t*>(p);
                a[mt][1] = *reinterpret_cast<const uint32_t*>(p + 8 * LDSH);
                a[mt][2] = *reinterpret_cast<const uint32_t*>(p + 8);
                a[mt][3] = *reinterpret_cast<const uint32_t*>(p + 8 * LDSH + 8);
            }
            #pragma unroll
            for (int nt = 0; nt < 8; nt++) {
                const __half* pb = &Bs[buf][(wn0 + nt * 8 + g) * LDSH + ks * 16 + 2 * tig];
                b[nt][0] = *reinterpret_cast<const uint32_t*>(pb);
                b[nt][1] = *reinterpret_cast<const uint32_t*>(pb + 8);
            }
            #pragma unroll
            for (int mt = 0; mt < 4; mt++)
                #pragma unroll
                for (int nt = 0; nt < 8; nt++)
                    mma16(acc[mt][nt], a[mt], b[nt]);
        }
    };

    {
        float4 av[8];
        ldgA(0, av);
        cpB(0, 0);
        stsA(0, av);
        CP_WAIT0();
        __syncthreads();
    }

    const int NC = K / BK;                       // 16
    for (int c = 0; c < NC; c++) {
        float4 av[8];
        const bool more = (c + 1 < NC);
        if (more) {
            ldgA(c + 1, av);
            cpB(c + 1, (c + 1) & 1);
        }
        compute(c & 1);
        if (more) {
            stsA((c + 1) & 1, av);
            CP_WAIT0();
            __syncthreads();
        }
    }

    #pragma unroll
    for (int mt = 0; mt < 4; mt++) {
        int r0 = blockM + wm0 + mt * 16 + g;
        int r1 = r0 + 8;
        #pragma unroll
        for (int nt = 0; nt < 8; nt++) {
            int cb = blockN + wn0 + nt * 8 + 2 * tig;
            if (r0 < M)
                *reinterpret_cast<uint32_t*>(&C[(size_t)r0 * Ntot + cb]) =
                    f2h2(acc[mt][nt][0], acc[mt][nt][1]);
            if (r1 < M)
                *reinterpret_cast<uint32_t*>(&C[(size_t)r1 * Ntot + cb]) =
                    f2h2(acc[mt][nt][2], acc[mt][nt][3]);
        }
    }
}

// ===========================================================================
// GEMM2: 8 warps (2Mx4N), BM=128, BN=64, BK=16.
// A fp16 (h2) with relu in register staging; Bt fp16; C fp16.
// ===========================================================================
__global__ void __launch_bounds__(256)
gemm2_mma(const __half* __restrict__ A, const __half* __restrict__ Bt,
          __half* __restrict__ C, int M, int K, int Ntot)
{
    constexpr int BM = 128, BN = 64, BK = 16, LDSH = 24, WNT = 2;
    __shared__ __half As[2][BM * LDSH];
    __shared__ __half Bs[2][BN * LDSH];

    const int tid  = threadIdx.x;
    const int lane = tid & 31, wid = tid >> 5;
    const int g    = lane >> 2, tig = lane & 3;
    const int wm0  = (wid >> 2) * 64;
    const int wn0  = (wid & 3) * (BN / 4);
    const int blockM = blockIdx.y * BM;
    const int blockN = blockIdx.x * BN;

    const int arow = tid >> 1;                   // 0..127
    const int aq   = tid & 1;

    float acc[4][WNT][4];
    #pragma unroll
    for (int mt = 0; mt < 4; mt++)
        #pragma unroll
        for (int nt = 0; nt < WNT; nt++)
            #pragma unroll
            for (int i = 0; i < 4; i++) acc[mt][nt][i] = 0.f;

    const __half2 hzero = __floats2half2_rn(0.f, 0.f);

    auto ldgA = [&](int c, uint4* av) {
        const int k0 = c * BK;
        int r = blockM + arow;
        if (r < M)
            *av = *reinterpret_cast<const uint4*>(&A[(size_t)r * K + k0 + aq * 8]);
        else
            *av = make_uint4(0u, 0u, 0u, 0u);
    };
    auto stsA = [&](int buf, uint4 v) {
        __half2* h = reinterpret_cast<__half2*>(&v);
        #pragma unroll
        for (int i = 0; i < 4; i++) h[i] = __hmax2(h[i], hzero);   // relu
        *reinterpret_cast<uint4*>(&As[buf][arow * LDSH + aq * 8]) = v;
    };
    auto cpB = [&](int c, int buf) {
        const int k0 = c * BK;
        if (tid < BN * 2) {
            int r = tid >> 1, q = tid & 1;
            cp16(smem_u32(&Bs[buf][r * LDSH + q * 8]),
                 &Bt[(size_t)(blockN + r) * K + k0 + q * 8]);
        }
        CP_COMMIT();
    };
    auto compute = [&](int buf) {
        uint32_t a[4][4], b[WNT][2];
        #pragma unroll
        for (int mt = 0; mt < 4; mt++) {
            const __half* p = &As[buf][(wm0 + mt * 16 + g) * LDSH + 2 * tig];
            a[mt][0] = *reinterpret_cast<const uint32_t*>(p);
            a[mt][1] = *reinterpret_cast<const uint32_t*>(p + 8 * LDSH);
            a[mt][2] = *reinterpret_cast<const uint32_t*>(p + 8);
            a[mt][3] = *reinterpret_cast<const uint32_t*>(p + 8 * LDSH + 8);
        }
        #pragma unroll
        for (int nt = 0; nt < WNT; nt++) {
            const __half* pb = &Bs[buf][(wn0 + nt * 8 + g) * LDSH + 2 * tig];
            b[nt][0] = *reinterpret_cast<const uint32_t*>(pb);
            b[nt][1] = *reinterpret_cast<const uint32_t*>(pb + 8);
        }
        #pragma unroll
        for (int mt = 0; mt < 4; mt++)
            #pragma unroll
            for (int nt = 0; nt < WNT; nt++)
                mma16(acc[mt][nt], a[mt], b[nt]);
    };

    {
        uint4 av;
        ldgA(0, &av);
        cpB(0, 0);
        stsA(0, av);
        CP_WAIT0();
        __syncthreads();
    }

    const int NC = K / BK;
    for (int c = 0; c < NC; c++) {
        uint4 av;
        const bool more = (c + 1 < NC);
        if (more) {
            ldgA(c + 1, &av);
            cpB(c + 1, (c + 1) & 1);
        }
        compute(c & 1);
        if (more) {
            stsA((c + 1) & 1, av);
            CP_WAIT0();
            __syncthreads();
        }
    }

    #pragma unroll
    for (int mt = 0; mt < 4; mt++) {
        int r0 = blockM + wm0 + mt * 16 + g;
        int r1 = r0 + 8;
        #pragma unroll
        for (int nt = 0; nt < WNT; nt++) {
            int cb = blockN + wn0 + nt * 8 + 2 * tig;
            if (r0 < M)
                *reinterpret_cast<uint32_t*>(&C[(size_t)r0 * Ntot + cb]) =
                    f2h2(acc[mt][nt][0], acc[mt][nt][1]);
            if (r1 < M)
                *reinterpret_cast<uint32_t*>(&C[(size_t)r1 * Ntot + cb]) =
                    f2h2(acc[mt][nt][2], acc[mt][nt][3]);
        }
    }
}

// ===========================================================================
// Elementwise / indexing kernels
// ===========================================================================
__global__ void transpose_round2(const float* __restrict__ w1, __half* __restrict__ w1t,
                                 const float* __restrict__ w2, __half* __restrict__ w2t,
                                 int sz1, int n1, int k1, int sz2, int n2, int k2)
{
    int i = blockIdx.x * blockDim.x + threadIdx.x;
    if (i < sz1) {
        int k = i / n1, n = i % n1;
        w1t[(size_t)n * k1 + k] = __float2half_rn(w1[i]);
    } else if (i < sz1 + sz2) {
        int j = i - sz1;
        int k = j / n2, n = j % n2;
        w2t[(size_t)n * k2 + k] = __float2half_rn(w2[j]);
    }
}

// row_ptr from sorted row array
__global__ void build_rowptr(const int* __restrict__ row, int* __restrict__ rp,
                             int E, int N)
{
    int e = blockIdx.x * blockDim.x + threadIdx.x;
    if (e >= E) return;
    int r0 = row[e];
    int r1 = (e + 1 < E) ? row[e + 1] : N;
    for (int r = r0 + 1; r <= r1; r++) rp[r] = e + 1;
    if (e == 0)
        for (int r = 0; r <= r0; r++) rp[r] = 0;
}

// ---------------------------------------------------------------------------
// CSR SpMM, fp16 src -> fp16 dst (layer 1, F=256).
// T=32 threads/row, uint4 (8-half) per thread; fp32 accumulate; direct store.
// ---------------------------------------------------------------------------
__global__ void __launch_bounds__(256)
spmm_csr_h2h(const __half* __restrict__ src, const float* __restrict__ bias,
             const float* __restrict__ ew, const int* __restrict__ rp,
             const int* __restrict__ col, __half* __restrict__ dst, int N)
{
    constexpr int T = 32;                 // threads per row (8 halves each)
    constexpr int G = 256 / T;            // 8 rows per block
    const int g = threadIdx.x / T;
    const int f = threadIdx.x % T;
    const int r = blockIdx.x * G + g;
    if (r >= N) return;

    const int s = __ldg(&rp[r]);
    const int e_end = __ldg(&rp[r + 1]);

    float a[8];
    #pragma unroll
    for (int q = 0; q < 8; q++) a[q] = 0.f;
    const uint4* src4 = reinterpret_cast<const uint4*>(src) + f;   // row stride T

    int i = s;
    for (; i + 4 <= e_end; i += 4) {
        float w[4]; uint4 v[4];
        #pragma unroll
        for (int j = 0; j < 4; j++) {                // 4 LDG.128 in flight
            int c = __ldg(&col[i + j]);
            w[j]  = __ldg(&ew[i + j]);
            v[j]  = __ldg(&src4[(size_t)c * T]);
        }
        #pragma unroll
        for (int j = 0; j < 4; j++) acc8(a, v[j], w[j]);
    }
    for (; i < e_end; i++) {
        int c = __ldg(&col[i]);
        float w = __ldg(&ew[i]);
        uint4 v = __ldg(&src4[(size_t)c * T]);
        acc8(a, v, w);
    }

    const float4* bias4 = reinterpret_cast<const float4*>(bias);
    float4 b0 = __ldg(&bias4[2 * f]);
    float4 b1 = __ldg(&bias4[2 * f + 1]);
    uint4 o;
    o.x = f2h2(a[0] + b0.x, a[1] + b0.y);
    o.y = f2h2(a[2] + b0.z, a[3] + b0.w);
    o.z = f2h2(a[4] + b1.x, a[5] + b1.y);
    o.w = f2h2(a[6] + b1.z, a[7] + b1.w);
    *(reinterpret_cast<uint4*>(dst) + (size_t)r * T + f) = o;
}

// ---------------------------------------------------------------------------
// CSR SpMM, fp16 src -> fp32 dst (layer 2, F=64).
// T=8 threads/row, uint4 (8-half) per thread.
// ---------------------------------------------------------------------------
__global__ void __launch_bounds__(256)
spmm_csr_h2f(const __half* __restrict__ src, const float* __restrict__ bias,
             const float* __restrict__ ew, const int* __restrict__ rp,
             const int* __restrict__ col, float* __restrict__ dst, int N)
{
    constexpr int T = 8;                  // threads per row (8 halves each)
    constexpr int G = 256 / T;            // 32 rows per block
    const int g = threadIdx.x / T;
    const int f = threadIdx.x % T;
    const int r = blockIdx.x * G + g;
    if (r >= N) return;

    const int s = __ldg(&rp[r]);
    const int e_end = __ldg(&rp[r + 1]);

    float a[8];
    #pragma unroll
    for (int q = 0; q < 8; q++) a[q] = 0.f;
    const uint4* src4 = reinterpret_cast<const uint4*>(src) + f;

    int i = s;
    for (; i + 4 <= e_end; i += 4) {
        float w[4]; uint4 v[4];
        #pragma unroll
        for (int j = 0; j < 4; j++) {
            int c = __ldg(&col[i + j]);
            w[j]  = __ldg(&ew[i + j]);
            v[j]  = __ldg(&src4[(size_t)c * T]);
        }
        #pragma unroll
        for (int j = 0; j < 4; j++) acc8(a, v[j], w[j]);
    }
    for (; i < e_end; i++) {
        int c = __ldg(&col[i]);
        float w = __ldg(&ew[i]);
        uint4 v = __ldg(&src4[(size_t)c * T]);
        acc8(a, v, w);
    }

    const float4* bias4 = reinterpret_cast<const float4*>(bias);
    float4 b0 = __ldg(&bias4[2 * f]);
    float4 b1 = __ldg(&bias4[2 * f + 1]);
    float4* d = reinterpret_cast<float4*>(dst) + (size_t)r * (2 * T) + 2 * f;
    d[0] = make_float4(a[0] + b0.x, a[1] + b0.y, a[2] + b0.z, a[3] + b0.w);
    d[1] = make_float4(a[4] + b1.x, a[5] + b1.y, a[6] + b1.z, a[7] + b1.w);
}

// ===========================================================================
extern "C" void kernel_launch(void* const* d_in, const int* in_sizes, int n_in,
                              void* d_out, int out_size)
{
    const float* x   = (const float*)d_in[0];
    const float* w1  = (const float*)d_in[1];
    const float* b1  = (const float*)d_in[2];
    const float* w2  = (const float*)d_in[3];
    const float* b2  = (const float*)d_in[4];
    const float* ew  = (const float*)d_in[5];
    const int*   row = (const int*)d_in[6];
    const int*   col = (const int*)d_in[7];

    const int nhid  = in_sizes[2];            // 256
    const int nout  = in_sizes[4];            // 64
    const int nfeat = in_sizes[1] / nhid;     // 512
    const int n     = in_sizes[0] / nfeat;    // 50000
    const int E     = in_sizes[5];            // 800000

    void *p1, *p2, *p3, *p4, *p5, *p6;
    cudaGetSymbolAddress(&p1, g_h1);
    cudaGetSymbolAddress(&p2, g_h2);
    cudaGetSymbolAddress(&p3, g_h3);
    cudaGetSymbolAddress(&p4, g_w1t);
    cudaGetSymbolAddress(&p5, g_w2t);
    cudaGetSymbolAddress(&p6, g_rowptr);
    __half* h1  = (__half*)p1;
    __half* h2  = (__half*)p2;
    __half* h3  = (__half*)p3;
    __half* w1t = (__half*)p4;
    __half* w2t = (__half*)p5;
    int*    rp  = (int*)p6;
    float*  out = (float*)d_out;

    const int tilesM = (n + 127) / 128;                   // 391

    // 0) weight transposes (fp32 -> fp16) + row_ptr from sorted rows
    {
        int sz1 = nfeat * nhid, sz2 = nhid * nout;
        transpose_round2<<<(sz1 + sz2 + 255) / 256, 256>>>(
            w1, w1t, w2, w2t, sz1, nhid, nfeat, sz2, nout, nhid);
        build_rowptr<<<(E + 255) / 256, 256>>>(row, rp, E, n);
    }

    // 1) h1 = x @ W1   (BK=32, fp16 out)
    {
        dim3 grid(nhid / 128, tilesM);
        gemm1_mma<<<grid, 128>>>(x, w1t, h1, n, nfeat, nhid);
    }

    // 2) h2 = b1 + A @ h1   (CSR, T=32 x uint4)
    spmm_csr_h2h<<<(n + 7) / 8, 256>>>(h1, b1, ew, rp, col, h2, n);

    // 3) h3 = relu(h2) @ W2   (fp16 in/out)
    {
        dim3 grid(nout / 64, tilesM);
        gemm2_mma<<<grid, 256>>>(h2, w2t, h3, n, nhid, nout);
    }

    // 4) out = b2 + A @ h3   (CSR, T=8 x uint4, fp32 out)
    spmm_csr_h2f<<<(n + 31) / 32, 256>>>(h3, b2, ew, rp, col, out, n);
}